// round 12
// baseline (speedup 1.0000x reference)
#include <cuda_runtime.h>
#include <cuda_bf16.h>
#include <math.h>
#include <stdint.h>

#define D_MODEL 1024
#define SEQ     2048
#define NHEADS  16
#define HEADDIM 64
#define MAXB    2

// ---------------------------------------------------------------------------
// Device scratch
// ---------------------------------------------------------------------------
__device__ float g_q[MAXB * SEQ * D_MODEL];
__device__ float g_k[MAXB * SEQ * D_MODEL];
__device__ float g_v[MAXB * SEQ * D_MODEL];
__device__ float g_ctx[MAXB * SEQ * D_MODEL];
__device__ float g_attn[(size_t)MAXB * NHEADS * SEQ * SEQ];

// ---------------------------------------------------------------------------
// tf32 helpers
// ---------------------------------------------------------------------------
__device__ __forceinline__ uint32_t f2tf32(float x) {
    uint32_t r;
    asm("cvt.rna.tf32.f32 %0, %1;" : "=r"(r) : "f"(x));
    return r;
}

__device__ __forceinline__ float ex2(float x) {
    float r;
    asm("ex2.approx.f32 %0, %1;" : "=f"(r) : "f"(x));
    return r;
}

__device__ __forceinline__ void mma_tf32(float* c, const uint32_t* a, const uint32_t* b) {
    asm("mma.sync.aligned.m16n8k8.row.col.f32.tf32.tf32.f32 "
        "{%0,%1,%2,%3}, {%4,%5,%6,%7}, {%8,%9}, {%0,%1,%2,%3};"
        : "+f"(c[0]), "+f"(c[1]), "+f"(c[2]), "+f"(c[3])
        : "r"(a[0]), "r"(a[1]), "r"(a[2]), "r"(a[3]), "r"(b[0]), "r"(b[1]));
}

__device__ __forceinline__ void store_half4(uint4* slot, int half, uint2 v) {
    uint32_t* w = (uint32_t*)slot + half * 2;
    w[0] = v.x; w[1] = v.y;
}

// ---------------------------------------------------------------------------
// Projection GEMM (R10, passing): ping-pong SMEM + register staging, 2 CTA/SM
// ---------------------------------------------------------------------------
struct GemmSmem {
    uint4 AF[8][4][33];
    uint4 BF[8][4][33];
};

__device__ __forceinline__ void gemm_load_regs(
    const float* __restrict__ A, const float* __restrict__ W,
    int m0, int n0, int k0, int tid,
    float4* a_lo, float4* a_hi, float4* b_lo, float4* b_hi)
{
    #pragma unroll
    for (int i = 0; i < 2; i++) {
        int idx = tid + i * 256;
        int rp = idx >> 3, c4 = (idx & 7) * 4;
        const float* a0 = &A[(size_t)(m0 + (rp >> 3) * 16 + (rp & 7)) * D_MODEL + k0 + c4];
        a_lo[i] = *(const float4*)a0;
        a_hi[i] = *(const float4*)(a0 + 8 * D_MODEL);
        int rp2 = idx >> 5, c42 = (idx & 31) * 4;
        const float* b0 = &W[(size_t)(k0 + (rp2 >> 2) * 8 + (rp2 & 3)) * D_MODEL + n0 + c42];
        b_lo[i] = *(const float4*)b0;
        b_hi[i] = *(const float4*)(b0 + 4 * D_MODEL);
    }
}

__device__ __forceinline__ void gemm_store_smem(
    GemmSmem& s, int tid,
    const float4* a_lo, const float4* a_hi, const float4* b_lo, const float4* b_hi)
{
    #pragma unroll
    for (int i = 0; i < 2; i++) {
        int idx = tid + i * 256;
        int rp = idx >> 3, c4 = (idx & 7) * 4;
        int mt = rp >> 3, r8 = rp & 7;
        int kb  = c4 >> 3;
        int off = ((c4 >> 2) & 1) * 2;
        uint32_t* base = (uint32_t*)&s.AF[mt][kb][r8 * 4];
        *(uint2*)&base[0 * 4 + off] = make_uint2(f2tf32(a_lo[i].x), f2tf32(a_hi[i].x));
        *(uint2*)&base[1 * 4 + off] = make_uint2(f2tf32(a_lo[i].y), f2tf32(a_hi[i].y));
        *(uint2*)&base[2 * 4 + off] = make_uint2(f2tf32(a_lo[i].z), f2tf32(a_hi[i].z));
        *(uint2*)&base[3 * 4 + off] = make_uint2(f2tf32(a_lo[i].w), f2tf32(a_hi[i].w));
        int rp2 = idx >> 5, c42 = (idx & 31) * 4;
        int kb2 = rp2 >> 2, rq = rp2 & 3;
        int nt = c42 >> 3, gb = c42 & 7;
        int nt2 = nt >> 1, half = nt & 1;
        store_half4(&s.BF[nt2][kb2][(gb + 0) * 4 + rq], half,
                    make_uint2(f2tf32(b_lo[i].x), f2tf32(b_hi[i].x)));
        store_half4(&s.BF[nt2][kb2][(gb + 1) * 4 + rq], half,
                    make_uint2(f2tf32(b_lo[i].y), f2tf32(b_hi[i].y)));
        store_half4(&s.BF[nt2][kb2][(gb + 2) * 4 + rq], half,
                    make_uint2(f2tf32(b_lo[i].z), f2tf32(b_hi[i].z)));
        store_half4(&s.BF[nt2][kb2][(gb + 3) * 4 + rq], half,
                    make_uint2(f2tf32(b_lo[i].w), f2tf32(b_hi[i].w)));
    }
}

__device__ __forceinline__ void gemm_body(
    GemmSmem* bufs, const float* __restrict__ A, const float* __restrict__ W,
    const float* __restrict__ bias, float* __restrict__ C, int m0, int n0)
{
    const int tid  = threadIdx.x;
    const int warp = tid >> 5;
    const int lane = tid & 31;
    const int g    = lane >> 2;
    const int kq   = lane & 3;
    const int wm   = warp >> 1;
    const int wn   = warp & 1;

    float acc[2][8][4] = {};
    float4 a_lo[2], a_hi[2], b_lo[2], b_hi[2];

    gemm_load_regs(A, W, m0, n0, 0, tid, a_lo, a_hi, b_lo, b_hi);
    gemm_store_smem(bufs[0], tid, a_lo, a_hi, b_lo, b_hi);
    __syncthreads();

    const int NT = D_MODEL / 32;
    for (int kt = 0; kt < NT; kt++) {
        GemmSmem& cur = bufs[kt & 1];
        const bool has_next = (kt + 1 < NT);
        if (has_next)
            gemm_load_regs(A, W, m0, n0, (kt + 1) * 32, tid, a_lo, a_hi, b_lo, b_hi);

        #pragma unroll
        for (int kb = 0; kb < 4; kb++) {
            uint4 a[2];
            a[0] = cur.AF[wm * 2 + 0][kb][lane];
            a[1] = cur.AF[wm * 2 + 1][kb][lane];
            #pragma unroll
            for (int jn2 = 0; jn2 < 4; jn2++) {
                uint4 b2 = cur.BF[wn * 4 + jn2][kb][lane];
                #pragma unroll
                for (int im = 0; im < 2; im++) {
                    mma_tf32(acc[im][2 * jn2 + 0], (const uint32_t*)&a[im], (const uint32_t*)&b2.x);
                    mma_tf32(acc[im][2 * jn2 + 1], (const uint32_t*)&a[im], (const uint32_t*)&b2.z);
                }
            }
        }

        if (has_next)
            gemm_store_smem(bufs[(kt + 1) & 1], tid, a_lo, a_hi, b_lo, b_hi);
        __syncthreads();
    }

    #pragma unroll
    for (int im = 0; im < 2; im++) {
        int mb = m0 + wm * 32 + im * 16;
        #pragma unroll
        for (int jn = 0; jn < 8; jn++) {
            int n = n0 + wn * 64 + jn * 8 + 2 * kq;
            float b0 = bias[n], b1 = bias[n + 1];
            float* p0 = &C[(size_t)(mb + g) * D_MODEL + n];
            float* p1 = &C[(size_t)(mb + g + 8) * D_MODEL + n];
            p0[0] = acc[im][jn][0] + b0; p0[1] = acc[im][jn][1] + b1;
            p1[0] = acc[im][jn][2] + b0; p1[1] = acc[im][jn][3] + b1;
        }
    }
}

__global__ void __launch_bounds__(256, 2)
qkv_proj_tc(const float* __restrict__ A,
            const float* __restrict__ Wq, const float* __restrict__ bq,
            const float* __restrict__ Wk, const float* __restrict__ bk,
            const float* __restrict__ Wv, const float* __restrict__ bv,
            float* __restrict__ oq, float* __restrict__ ok, float* __restrict__ ov)
{
    extern __shared__ char smem_raw[];
    GemmSmem* bufs = (GemmSmem*)smem_raw;
    const int z = blockIdx.z;
    const float* W    = (z == 0) ? Wq : (z == 1) ? Wk : Wv;
    const float* bias = (z == 0) ? bq : (z == 1) ? bk : bv;
    float*       C    = (z == 0) ? oq : (z == 1) ? ok : ov;
    gemm_body(bufs, A, W, bias, C, blockIdx.y * 128, blockIdx.x * 128);
}

__global__ void __launch_bounds__(256, 2)
gemm_bias_tc(const float* __restrict__ A, const float* __restrict__ W,
             const float* __restrict__ bias, float* __restrict__ C)
{
    extern __shared__ char smem_raw[];
    GemmSmem* bufs = (GemmSmem*)smem_raw;
    gemm_body(bufs, A, W, bias, C, blockIdx.y * 128, blockIdx.x * 128);
}

// ---------------------------------------------------------------------------
// Fused attention: per CTA = 128-row strip x all 2048 keys of one (b,h).
// 512 threads = 16 warps (wm 0..3 x wn 0..3).
// Sweep 1: S=QK^T, exp, accumulate row sums (no stores).
// Sweep 2: recompute S, exp, multiply by invl, write normalized P once,
//          round-trip p-frags via SMEM, accumulate O = P@V in registers.
// ---------------------------------------------------------------------------
struct FusedSmem {
    uint4 QF[8][8][33];    // Q A-frags  [mt][kb][lane]
    uint4 KF[8][8][33];    // paired K B-frags [nt2][kb][lane]   (keys as N)
    uint4 VF[4][16][33];   // paired V B-frags [nt2][kb][lane]   (keys as K)
    uint4 PF[8][16][33];   // P A-frags  [mt][kbp][lane]
    float red[4][128];
    float sinvl[128];
};

// p-frag scatter index (R5-validated mapping)
__device__ __forceinline__ int frag_word(int r, int c) {
    return (((r & 7) << 2) + (c & 3)) * 4 + ((r >> 3) & 1) + (((c >> 2) & 1) << 1);
}

__device__ __forceinline__ void fa_load_k(
    const float* __restrict__ kbase, int n0, int tid, float4* k_lo, float4* k_hi)
{
    #pragma unroll
    for (int i = 0; i < 2; i++) {
        int idx = tid + i * 512;
        int n  = idx >> 3;
        int c8 = (idx & 7) * 8;
        const float* p = &kbase[(size_t)(n0 + n) * D_MODEL + c8];
        k_lo[i] = *(const float4*)p;
        k_hi[i] = *(const float4*)(p + 4);
    }
}

__device__ __forceinline__ void fa_store_k(
    uint4 (*KF)[8][33], int tid, const float4* k_lo, const float4* k_hi)
{
    #pragma unroll
    for (int i = 0; i < 2; i++) {
        int idx = tid + i * 512;
        int n  = idx >> 3;
        int c8 = (idx & 7) * 8;
        int nt  = n >> 3;           // 0..15
        int gg  = n & 7;
        int kbk = c8 >> 3;
        int nt2 = nt >> 1, half = nt & 1;
        store_half4(&KF[nt2][kbk][gg * 4 + 0], half, make_uint2(f2tf32(k_lo[i].x), f2tf32(k_hi[i].x)));
        store_half4(&KF[nt2][kbk][gg * 4 + 1], half, make_uint2(f2tf32(k_lo[i].y), f2tf32(k_hi[i].y)));
        store_half4(&KF[nt2][kbk][gg * 4 + 2], half, make_uint2(f2tf32(k_lo[i].z), f2tf32(k_hi[i].z)));
        store_half4(&KF[nt2][kbk][gg * 4 + 3], half, make_uint2(f2tf32(k_lo[i].w), f2tf32(k_hi[i].w)));
    }
}

__device__ __forceinline__ void fa_load_v(
    const float* __restrict__ vbase, int n0, int tid, float4* v_lo, float4* v_hi)
{
    #pragma unroll
    for (int i = 0; i < 2; i++) {
        int idx = tid + i * 512;
        int rp = idx >> 4;            // 0..63 key-pair groups
        int c4 = (idx & 15) * 4;      // d 0..60
        int key = (rp >> 2) * 8 + (rp & 3);
        const float* p = &vbase[(size_t)(n0 + key) * D_MODEL + c4];
        v_lo[i] = *(const float4*)p;
        v_hi[i] = *(const float4*)(p + 4 * D_MODEL);
    }
}

__device__ __forceinline__ void fa_store_v(
    uint4 (*VF)[16][33], int tid, const float4* v_lo, const float4* v_hi)
{
    #pragma unroll
    for (int i = 0; i < 2; i++) {
        int idx = tid + i * 512;
        int rp = idx >> 4;
        int c4 = (idx & 15) * 4;
        int kbk = rp >> 2;            // 0..15
        int rq  = rp & 3;
        int nt = c4 >> 3, gb = c4 & 7;
        int nt2 = nt >> 1, half = nt & 1;
        store_half4(&VF[nt2][kbk][(gb + 0) * 4 + rq], half, make_uint2(f2tf32(v_lo[i].x), f2tf32(v_hi[i].x)));
        store_half4(&VF[nt2][kbk][(gb + 1) * 4 + rq], half, make_uint2(f2tf32(v_lo[i].y), f2tf32(v_hi[i].y)));
        store_half4(&VF[nt2][kbk][(gb + 2) * 4 + rq], half, make_uint2(f2tf32(v_lo[i].z), f2tf32(v_hi[i].z)));
        store_half4(&VF[nt2][kbk][(gb + 3) * 4 + rq], half, make_uint2(f2tf32(v_lo[i].w), f2tf32(v_hi[i].w)));
    }
}

__global__ void __launch_bounds__(512, 1)
attn_fused(const float* __restrict__ qb, const float* __restrict__ kb_,
           const float* __restrict__ vb, const float* __restrict__ scale_ptr,
           float* __restrict__ attn, float* __restrict__ ctx)
{
    extern __shared__ char smem_raw[];
    FusedSmem& sm = *(FusedSmem*)smem_raw;

    const int tid  = threadIdx.x;
    const int warp = tid >> 5;
    const int lane = tid & 31;
    const int g    = lane >> 2;
    const int kq   = lane & 3;
    const int wm   = warp >> 2;   // 0..3
    const int wn   = warp & 3;    // 0..3

    const int bh = blockIdx.y;
    const int b  = bh >> 4;
    const int h  = bh & 15;
    const int m0 = blockIdx.x * 128;

    const float sc = scale_ptr[0] * 1.44269504088896f;

    const float* qbase = qb  + (size_t)(b * SEQ + m0) * D_MODEL + h * HEADDIM;
    const float* kbase = kb_ + (size_t)b * SEQ * D_MODEL + h * HEADDIM;
    const float* vbase = vb  + (size_t)b * SEQ * D_MODEL + h * HEADDIM;
    float* pstrip = attn + ((size_t)bh * SEQ + m0) * SEQ;

    // ---- Q strip 128x64 -> QF (once) ----
    #pragma unroll
    for (int k0 = 0; k0 < 64; k0 += 32) {
        int idx = tid;                    // 512 slots per 128x32 tile
        int rp = idx >> 3;
        int c4 = (idx & 7) * 4;
        int mt = rp >> 3;
        int r8 = rp & 7;
        const float* a0 = &qbase[(size_t)(mt * 16 + r8) * D_MODEL + k0 + c4];
        float4 vlo = *(const float4*)a0;
        float4 vhi = *(const float4*)(a0 + 8 * D_MODEL);
        int kb  = (k0 + c4) >> 3;
        int off = ((c4 >> 2) & 1) * 2;
        uint32_t* base = (uint32_t*)&sm.QF[mt][kb][r8 * 4];
        *(uint2*)&base[0 * 4 + off] = make_uint2(f2tf32(vlo.x), f2tf32(vhi.x));
        *(uint2*)&base[1 * 4 + off] = make_uint2(f2tf32(vlo.y), f2tf32(vhi.y));
        *(uint2*)&base[2 * 4 + off] = make_uint2(f2tf32(vlo.z), f2tf32(vhi.z));
        *(uint2*)&base[3 * 4 + off] = make_uint2(f2tf32(vlo.w), f2tf32(vhi.w));
    }

    const int NIT = SEQ / 128;
    float4 k_lo[2], k_hi[2], v_lo[2], v_hi[2];

    // ================= Sweep 1: row sums =================
    float l_acc[2][2] = {};

    fa_load_k(kbase, 0, tid, k_lo, k_hi);
    fa_store_k(sm.KF, tid, k_lo, k_hi);
    __syncthreads();

    for (int iter = 0; iter < NIT; iter++) {
        const bool has_next = (iter + 1 < NIT);
        if (has_next) fa_load_k(kbase, (iter + 1) * 128, tid, k_lo, k_hi);

        float acc[2][4][4] = {};
        #pragma unroll
        for (int kb = 0; kb < 8; kb++) {
            uint4 a[2];
            a[0] = sm.QF[wm * 2 + 0][kb][lane];
            a[1] = sm.QF[wm * 2 + 1][kb][lane];
            #pragma unroll
            for (int jn2 = 0; jn2 < 2; jn2++) {
                uint4 kf = sm.KF[wn * 2 + jn2][kb][lane];
                #pragma unroll
                for (int im = 0; im < 2; im++) {
                    mma_tf32(acc[im][2 * jn2 + 0], (const uint32_t*)&a[im], (const uint32_t*)&kf.x);
                    mma_tf32(acc[im][2 * jn2 + 1], (const uint32_t*)&a[im], (const uint32_t*)&kf.z);
                }
            }
        }
        #pragma unroll
        for (int im = 0; im < 2; im++)
            #pragma unroll
            for (int jn = 0; jn < 4; jn++) {
                l_acc[im][0] += ex2(acc[im][jn][0] * sc) + ex2(acc[im][jn][1] * sc);
                l_acc[im][1] += ex2(acc[im][jn][2] * sc) + ex2(acc[im][jn][3] * sc);
            }

        __syncthreads();
        if (has_next) fa_store_k(sm.KF, tid, k_lo, k_hi);
        __syncthreads();
    }

    // ---- reduce l -> sinvl ----
    #pragma unroll
    for (int im = 0; im < 2; im++)
        #pragma unroll
        for (int rh = 0; rh < 2; rh++) {
            l_acc[im][rh] += __shfl_xor_sync(0xffffffff, l_acc[im][rh], 1);
            l_acc[im][rh] += __shfl_xor_sync(0xffffffff, l_acc[im][rh], 2);
        }
    if (kq == 0) {
        #pragma unroll
        for (int im = 0; im < 2; im++)
            #pragma unroll
            for (int rh = 0; rh < 2; rh++)
                sm.red[wn][wm * 32 + im * 16 + rh * 8 + g] = l_acc[im][rh];
    }
    __syncthreads();
    if (tid < 128)
        sm.sinvl[tid] = 1.0f / (sm.red[0][tid] + sm.red[1][tid] +
                                sm.red[2][tid] + sm.red[3][tid]);
    __syncthreads();

    // ================= Sweep 2: write P, accumulate O =================
    float acc_o[2][2][4] = {};
    const float il_row0[2] = { sm.sinvl[wm * 32 + 0 * 16 + g], sm.sinvl[wm * 32 + 0 * 16 + g + 8] };
    const float il_row1[2] = { sm.sinvl[wm * 32 + 1 * 16 + g], sm.sinvl[wm * 32 + 1 * 16 + g + 8] };

    fa_load_k(kbase, 0, tid, k_lo, k_hi);
    fa_load_v(vbase, 0, tid, v_lo, v_hi);
    fa_store_k(sm.KF, tid, k_lo, k_hi);
    fa_store_v(sm.VF, tid, v_lo, v_hi);
    __syncthreads();

    for (int iter = 0; iter < NIT; iter++) {
        const int n0 = iter * 128;
        const bool has_next = (iter + 1 < NIT);
        if (has_next) {
            fa_load_k(kbase, n0 + 128, tid, k_lo, k_hi);
            fa_load_v(vbase, n0 + 128, tid, v_lo, v_hi);
        }

        // --- S MMA ---
        float acc[2][4][4] = {};
        #pragma unroll
        for (int kb = 0; kb < 8; kb++) {
            uint4 a[2];
            a[0] = sm.QF[wm * 2 + 0][kb][lane];
            a[1] = sm.QF[wm * 2 + 1][kb][lane];
            #pragma unroll
            for (int jn2 = 0; jn2 < 2; jn2++) {
                uint4 kf = sm.KF[wn * 2 + jn2][kb][lane];
                #pragma unroll
                for (int im = 0; im < 2; im++) {
                    mma_tf32(acc[im][2 * jn2 + 0], (const uint32_t*)&a[im], (const uint32_t*)&kf.x);
                    mma_tf32(acc[im][2 * jn2 + 1], (const uint32_t*)&a[im], (const uint32_t*)&kf.z);
                }
            }
        }

        // --- exp, normalize, write P, scatter p-frags to PF ---
        #pragma unroll
        for (int im = 0; im < 2; im++) {
            const float il0 = (im == 0) ? il_row0[0] : il_row1[0];
            const float il1 = (im == 0) ? il_row0[1] : il_row1[1];
            int mt = wm * 2 + im;
            int mb = wm * 32 + im * 16;
            #pragma unroll
            for (int jn = 0; jn < 4; jn++) {
                int c = wn * 32 + jn * 8 + 2 * kq;     // within-tile key col
                int kbp = wn * 4 + jn;
                float p0 = ex2(acc[im][jn][0] * sc) * il0;
                float p1 = ex2(acc[im][jn][1] * sc) * il0;
                float p2 = ex2(acc[im][jn][2] * sc) * il1;
                float p3 = ex2(acc[im][jn][3] * sc) * il1;
                *(float2*)&pstrip[(size_t)(mb + g) * SEQ + n0 + c]     = make_float2(p0, p1);
                *(float2*)&pstrip[(size_t)(mb + g + 8) * SEQ + n0 + c] = make_float2(p2, p3);
                uint32_t* pfb = (uint32_t*)&sm.PF[mt][kbp][0];
                int c0 = 2 * kq, c1 = 2 * kq + 1;
                pfb[frag_word(g,     c0)] = f2tf32(p0);
                pfb[frag_word(g,     c1)] = f2tf32(p1);
                pfb[frag_word(g + 8, c0)] = f2tf32(p2);
                pfb[frag_word(g + 8, c1)] = f2tf32(p3);
            }
        }
        __syncthreads();   // PF complete; KF reads done

        // --- PV MMA: O += P(tile) @ V(tile) ---
        #pragma unroll
        for (int kb = 0; kb < 16; kb++) {
            uint4 a[2];
            a[0] = sm.PF[wm * 2 + 0][kb][lane];
            a[1] = sm.PF[wm * 2 + 1][kb][lane];
            uint4 vf = sm.VF[wn][kb][lane];
            #pragma unroll
            for (int im = 0; im < 2; im++) {
                mma_tf32(acc_o[im][0], (const uint32_t*)&a[im], (const uint32_t*)&vf.x);
                mma_tf32(acc_o[im][1], (const uint32_t*)&a[im], (const uint32_t*)&vf.z);
            }
        }
        __syncthreads();   // VF/PF reads done

        if (has_next) {
            fa_store_k(sm.KF, tid, k_lo, k_hi);
            fa_store_v(sm.VF, tid, v_lo, v_hi);
        }
        __syncthreads();
    }

    // ---- write O (already normalized) ----
    #pragma unroll
    for (int im = 0; im < 2; im++) {
        int mb = b * SEQ + m0 + wm * 32 + im * 16;
        #pragma unroll
        for (int jn = 0; jn < 2; jn++) {
            int d = h * HEADDIM + wn * 16 + jn * 8 + 2 * kq;
            float* p0 = &ctx[(size_t)(mb + g) * D_MODEL + d];
            float* p1 = &ctx[(size_t)(mb + g + 8) * D_MODEL + d];
            p0[0] = acc_o[im][jn][0]; p0[1] = acc_o[im][jn][1];
            p1[0] = acc_o[im][jn][2]; p1[1] = acc_o[im][jn][3];
        }
    }
}

// ---------------------------------------------------------------------------
// Launch
// ---------------------------------------------------------------------------
extern "C" void kernel_launch(void* const* d_in, const int* in_sizes, int n_in,
                              void* d_out, int out_size)
{
    const float* Q     = (const float*)d_in[0];
    const float* Wq    = (const float*)d_in[1];
    const float* bq    = (const float*)d_in[2];
    const float* Wk    = (const float*)d_in[3];
    const float* bk    = (const float*)d_in[4];
    const float* Wv    = (const float*)d_in[5];
    const float* bv    = (const float*)d_in[6];
    const float* Wo    = (const float*)d_in[7];
    const float* bo    = (const float*)d_in[8];
    const float* scale = (const float*)d_in[9];

    const int M = in_sizes[0] / D_MODEL;
    const int B = M / SEQ;

    float* out = (float*)d_out;

    float *qp, *kp, *vp, *cp, *ap;
    cudaGetSymbolAddress((void**)&qp, g_q);
    cudaGetSymbolAddress((void**)&kp, g_k);
    cudaGetSymbolAddress((void**)&vp, g_v);
    cudaGetSymbolAddress((void**)&cp, g_ctx);
    cudaGetSymbolAddress((void**)&ap, g_attn);

    const size_t out_elems = (size_t)M * D_MODEL;
    float* attn = ((size_t)out_size > out_elems) ? (out + out_elems) : ap;

    const int gemm_smem  = (int)(2 * sizeof(GemmSmem));
    const int fused_smem = (int)sizeof(FusedSmem);
    cudaFuncSetAttribute(qkv_proj_tc, cudaFuncAttributeMaxDynamicSharedMemorySize, gemm_smem);
    cudaFuncSetAttribute(gemm_bias_tc, cudaFuncAttributeMaxDynamicSharedMemorySize, gemm_smem);
    cudaFuncSetAttribute(attn_fused, cudaFuncAttributeMaxDynamicSharedMemorySize, fused_smem);

    dim3 gqkv(D_MODEL / 128, M / 128, 3);
    qkv_proj_tc<<<gqkv, 256, gemm_smem>>>(Q, Wq, bq, Wk, bk, Wv, bv, qp, kp, vp);

    dim3 gfa(SEQ / 128, B * NHEADS);   // (16, 32)
    attn_fused<<<gfa, 512, fused_smem>>>(qp, kp, vp, scale, attn, cp);

    dim3 gproj(D_MODEL / 128, M / 128);
    gemm_bias_tc<<<gproj, 256, gemm_smem>>>(cp, Wo, bo, out);
}

// round 13
// speedup vs baseline: 1.4727x; 1.4727x over previous
#include <cuda_runtime.h>
#include <cuda_bf16.h>
#include <cuda_fp16.h>
#include <math.h>
#include <stdint.h>

#define D_MODEL 1024
#define SEQ     2048
#define NHEADS  16
#define HEADDIM 64
#define MAXB    2

// ---------------------------------------------------------------------------
// Device scratch
// ---------------------------------------------------------------------------
__device__ float g_q[MAXB * SEQ * D_MODEL];
__device__ float g_k[MAXB * SEQ * D_MODEL];
__device__ float g_v[MAXB * SEQ * D_MODEL];
__device__ float g_ctx[MAXB * SEQ * D_MODEL];
__device__ float g_invl[MAXB * NHEADS * SEQ];
__device__ float g_attn[(size_t)MAXB * NHEADS * SEQ * SEQ];

// ---------------------------------------------------------------------------
// helpers
// ---------------------------------------------------------------------------
__device__ __forceinline__ uint32_t f2h2(float a, float b) {
    __half2 h = __floats2half2_rn(a, b);
    return *(uint32_t*)&h;
}

__device__ __forceinline__ float ex2(float x) {
    float r;
    asm("ex2.approx.f32 %0, %1;" : "=f"(r) : "f"(x));
    return r;
}

// m16n8k16 fp16 MMA, fp32 accumulate. a: 4 regs, b: 2 regs.
__device__ __forceinline__ void mma_f16(float* c, const uint32_t* a, const uint32_t* b) {
    asm("mma.sync.aligned.m16n8k16.row.col.f32.f16.f16.f32 "
        "{%0,%1,%2,%3}, {%4,%5,%6,%7}, {%8,%9}, {%0,%1,%2,%3};"
        : "+f"(c[0]), "+f"(c[1]), "+f"(c[2]), "+f"(c[3])
        : "r"(a[0]), "r"(a[1]), "r"(a[2]), "r"(a[3]), "r"(b[0]), "r"(b[1]));
}

// ---------------------------------------------------------------------------
// Projection GEMM (fp16 k16): ping-pong SMEM + register staging, 2 CTA/SM
// A-frag layout: AF[mt][kb16][lane] uint4 = {a0,a1,a2,a3}
//   a0 = A[g][2kq,2kq+1], a1 = A[g+8][..], a2 = A[g][2kq+8,+9], a3 = A[g+8][..]
// B-frag layout: BF[nt2][kb16][lane] uint4 = {b0,b1 of even nt, b0,b1 of odd nt}
//   b0 = B[2kq,2kq+1][n=g], b1 = B[2kq+8,2kq+9][n=g]  (half2 along k)
// ---------------------------------------------------------------------------
struct GemmSmem {
    uint4 AF[8][2][33];
    uint4 BF[8][2][33];
};

__device__ __forceinline__ void gemm_load_regs(
    const float* __restrict__ A, const float* __restrict__ W,
    int m0, int n0, int k0, int tid,
    float4* a_lo, float4* a_hi, float4* b_lo, float4* b_hi)
{
    #pragma unroll
    for (int i = 0; i < 2; i++) {
        int idx = tid + i * 256;
        int rp = idx >> 3, c4 = (idx & 7) * 4;
        const float* a0 = &A[(size_t)(m0 + (rp >> 3) * 16 + (rp & 7)) * D_MODEL + k0 + c4];
        a_lo[i] = *(const float4*)a0;
        a_hi[i] = *(const float4*)(a0 + 8 * D_MODEL);
        // B: k-row PAIRS (2*rp2, 2*rp2+1) for half2-along-k fragments
        int rp2 = idx >> 5, c42 = (idx & 31) * 4;
        const float* b0 = &W[(size_t)(k0 + 2 * rp2) * D_MODEL + n0 + c42];
        b_lo[i] = *(const float4*)b0;                 // k even row
        b_hi[i] = *(const float4*)(b0 + D_MODEL);     // k odd row
    }
}

__device__ __forceinline__ void a_frag_store(
    uint32_t* w, int r8, int c4, const float4& vlo, const float4& vhi)
{
    // w = base of [33]-uint4 lane array (132 words) for (mt, kb)
    int cc  = c4 & 15;
    int kq0 = (cc & 7) >> 1;          // 0 or 2
    int rb  = (cc >= 8) ? 2 : 0;
    int l0 = (r8 * 4 + kq0) * 4;
    int l1 = (r8 * 4 + kq0 + 1) * 4;
    w[l0 + rb]     = f2h2(vlo.x, vlo.y);
    w[l0 + rb + 1] = f2h2(vhi.x, vhi.y);
    w[l1 + rb]     = f2h2(vlo.z, vlo.w);
    w[l1 + rb + 1] = f2h2(vhi.z, vhi.w);
}

__device__ __forceinline__ void gemm_store_smem(
    GemmSmem& s, int tid,
    const float4* a_lo, const float4* a_hi, const float4* b_lo, const float4* b_hi)
{
    #pragma unroll
    for (int i = 0; i < 2; i++) {
        int idx = tid + i * 256;
        int rp = idx >> 3, c4 = (idx & 7) * 4;
        int mt = rp >> 3, r8 = rp & 7;
        a_frag_store((uint32_t*)&s.AF[mt][c4 >> 4][0], r8, c4, a_lo[i], a_hi[i]);

        int rp2 = idx >> 5, c42 = (idx & 31) * 4;
        int kb = rp2 >> 3;
        int tt = rp2 & 7;
        int kq = tt & 3, regsel = tt >> 2;
        float be[4] = {b_lo[i].x, b_lo[i].y, b_lo[i].z, b_lo[i].w};
        float bo[4] = {b_hi[i].x, b_hi[i].y, b_hi[i].z, b_hi[i].w};
        #pragma unroll
        for (int j = 0; j < 4; j++) {
            int n = c42 + j;
            int nt = n >> 3, gg = n & 7;
            uint32_t* w = (uint32_t*)&s.BF[nt >> 1][kb][0];
            w[(gg * 4 + kq) * 4 + (nt & 1) * 2 + regsel] = f2h2(be[j], bo[j]);
        }
    }
}

__device__ __forceinline__ void gemm_body(
    GemmSmem* bufs, const float* __restrict__ A, const float* __restrict__ W,
    const float* __restrict__ bias, float* __restrict__ C, int m0, int n0)
{
    const int tid  = threadIdx.x;
    const int warp = tid >> 5;
    const int lane = tid & 31;
    const int g    = lane >> 2;
    const int kq   = lane & 3;
    const int wm   = warp >> 1;
    const int wn   = warp & 1;

    float acc[2][8][4] = {};
    float4 a_lo[2], a_hi[2], b_lo[2], b_hi[2];

    gemm_load_regs(A, W, m0, n0, 0, tid, a_lo, a_hi, b_lo, b_hi);
    gemm_store_smem(bufs[0], tid, a_lo, a_hi, b_lo, b_hi);
    __syncthreads();

    const int NT = D_MODEL / 32;
    for (int kt = 0; kt < NT; kt++) {
        GemmSmem& cur = bufs[kt & 1];
        const bool has_next = (kt + 1 < NT);
        if (has_next)
            gemm_load_regs(A, W, m0, n0, (kt + 1) * 32, tid, a_lo, a_hi, b_lo, b_hi);

        #pragma unroll
        for (int kb = 0; kb < 2; kb++) {
            uint4 a[2];
            a[0] = cur.AF[wm * 2 + 0][kb][lane];
            a[1] = cur.AF[wm * 2 + 1][kb][lane];
            #pragma unroll
            for (int jn2 = 0; jn2 < 4; jn2++) {
                uint4 b2 = cur.BF[wn * 4 + jn2][kb][lane];
                #pragma unroll
                for (int im = 0; im < 2; im++) {
                    mma_f16(acc[im][2 * jn2 + 0], (const uint32_t*)&a[im], (const uint32_t*)&b2.x);
                    mma_f16(acc[im][2 * jn2 + 1], (const uint32_t*)&a[im], (const uint32_t*)&b2.z);
                }
            }
        }

        if (has_next)
            gemm_store_smem(bufs[(kt + 1) & 1], tid, a_lo, a_hi, b_lo, b_hi);
        __syncthreads();
    }

    #pragma unroll
    for (int im = 0; im < 2; im++) {
        int mb = m0 + wm * 32 + im * 16;
        #pragma unroll
        for (int jn = 0; jn < 8; jn++) {
            int n = n0 + wn * 64 + jn * 8 + 2 * kq;
            float b0 = bias[n], b1 = bias[n + 1];
            float* p0 = &C[(size_t)(mb + g) * D_MODEL + n];
            float* p1 = &C[(size_t)(mb + g + 8) * D_MODEL + n];
            p0[0] = acc[im][jn][0] + b0; p0[1] = acc[im][jn][1] + b1;
            p1[0] = acc[im][jn][2] + b0; p1[1] = acc[im][jn][3] + b1;
        }
    }
}

__global__ void __launch_bounds__(256, 2)
qkv_proj_tc(const float* __restrict__ A,
            const float* __restrict__ Wq, const float* __restrict__ bq,
            const float* __restrict__ Wk, const float* __restrict__ bk,
            const float* __restrict__ Wv, const float* __restrict__ bv,
            float* __restrict__ oq, float* __restrict__ ok, float* __restrict__ ov)
{
    extern __shared__ char smem_raw[];
    GemmSmem* bufs = (GemmSmem*)smem_raw;
    const int z = blockIdx.z;
    const float* W    = (z == 0) ? Wq : (z == 1) ? Wk : Wv;
    const float* bias = (z == 0) ? bq : (z == 1) ? bk : bv;
    float*       C    = (z == 0) ? oq : (z == 1) ? ok : ov;
    gemm_body(bufs, A, W, bias, C, blockIdx.y * 128, blockIdx.x * 128);
}

__global__ void __launch_bounds__(256, 2)
gemm_bias_tc(const float* __restrict__ A, const float* __restrict__ W,
             const float* __restrict__ bias, float* __restrict__ C)
{
    extern __shared__ char smem_raw[];
    GemmSmem* bufs = (GemmSmem*)smem_raw;
    gemm_body(bufs, A, W, bias, C, blockIdx.y * 128, blockIdx.x * 128);
}

// ---------------------------------------------------------------------------
// scores+exp fused (fp16 k16): ping-pong K; CTA = 128-row strip x 2048 keys
// ---------------------------------------------------------------------------
struct ScoresSmem {
    uint4 QF[8][4][33];       // Q A-frags [mt][kb16][lane]
    uint4 KF[2][8][4][33];    // paired K B-frags [buf][nt2][kb16][lane]
    float red[2][128];
};

__device__ __forceinline__ void scores_load_k(
    const float* __restrict__ kbase, int n0, int tid, float4* k_lo, float4* k_hi)
{
    #pragma unroll
    for (int i = 0; i < 4; i++) {
        int idx = tid + i * 256;
        int n  = idx >> 3;
        int c8 = (idx & 7) * 8;
        const float* p = &kbase[(size_t)(n0 + n) * D_MODEL + c8];
        k_lo[i] = *(const float4*)p;
        k_hi[i] = *(const float4*)(p + 4);
    }
}

__device__ __forceinline__ void scores_store_k(
    uint4 (*KF)[4][33], int tid, const float4* k_lo, const float4* k_hi)
{
    #pragma unroll
    for (int i = 0; i < 4; i++) {
        int idx = tid + i * 256;
        int n  = idx >> 3;
        int c8 = (idx & 7) * 8;          // K row gives k-consecutive values
        int nt = n >> 3, gg = n & 7;
        int nt2 = nt >> 1, half = nt & 1;
        int kb = c8 >> 4;
        int regsel = (c8 >> 3) & 1;
        uint32_t* w = (uint32_t*)&KF[nt2][kb][0];
        // k-pairs j=0..3: kq = j (t0 multiple of 4)
        w[(gg * 4 + 0) * 4 + half * 2 + regsel] = f2h2(k_lo[i].x, k_lo[i].y);
        w[(gg * 4 + 1) * 4 + half * 2 + regsel] = f2h2(k_lo[i].z, k_lo[i].w);
        w[(gg * 4 + 2) * 4 + half * 2 + regsel] = f2h2(k_hi[i].x, k_hi[i].y);
        w[(gg * 4 + 3) * 4 + half * 2 + regsel] = f2h2(k_hi[i].z, k_hi[i].w);
    }
}

__global__ void __launch_bounds__(256, 2)
scores_exp_tc(const float* __restrict__ qb, const float* __restrict__ kb_,
              const float* __restrict__ scale_ptr, float* __restrict__ attn,
              float* __restrict__ invl_out)
{
    extern __shared__ char smem_raw[];
    ScoresSmem& sm = *(ScoresSmem*)smem_raw;

    const int tid  = threadIdx.x;
    const int warp = tid >> 5;
    const int lane = tid & 31;
    const int g    = lane >> 2;
    const int kq   = lane & 3;
    const int wm   = warp >> 1;
    const int wn   = warp & 1;

    const int bh = blockIdx.y;
    const int b  = bh >> 4;
    const int h  = bh & 15;
    const int m0 = blockIdx.x * 128;

    const float sc = scale_ptr[0] * 1.44269504088896f;

    const float* qbase = qb  + (size_t)(b * SEQ + m0) * D_MODEL + h * HEADDIM;
    const float* kbase = kb_ + (size_t)b * SEQ * D_MODEL + h * HEADDIM;
    float* pstrip = attn + ((size_t)bh * SEQ + m0) * SEQ;

    // ---- Q strip 128x64 -> QF (once) ----
    #pragma unroll
    for (int k0 = 0; k0 < 64; k0 += 32) {
        #pragma unroll
        for (int i = 0; i < 2; i++) {
            int idx = tid + i * 256;
            int rp = idx >> 3;
            int c4 = (idx & 7) * 4;
            int mt = rp >> 3;
            int r8 = rp & 7;
            const float* a0 = &qbase[(size_t)(mt * 16 + r8) * D_MODEL + k0 + c4];
            float4 vlo = *(const float4*)a0;
            float4 vhi = *(const float4*)(a0 + 8 * D_MODEL);
            a_frag_store((uint32_t*)&sm.QF[mt][(k0 + c4) >> 4][0], r8, c4, vlo, vhi);
        }
    }

    float l_acc[2][2] = {};
    float4 k_lo[4], k_hi[4];

    scores_load_k(kbase, 0, tid, k_lo, k_hi);
    scores_store_k(sm.KF[0], tid, k_lo, k_hi);
    __syncthreads();

    const int NIT = SEQ / 128;
    for (int iter = 0; iter < NIT; iter++) {
        const int n0 = iter * 128;
        const bool has_next = (iter + 1 < NIT);
        if (has_next) scores_load_k(kbase, n0 + 128, tid, k_lo, k_hi);

        uint4 (*KFc)[4][33] = sm.KF[iter & 1];
        float acc[2][8][4] = {};
        #pragma unroll
        for (int kb = 0; kb < 4; kb++) {
            uint4 a[2];
            a[0] = sm.QF[wm * 2 + 0][kb][lane];
            a[1] = sm.QF[wm * 2 + 1][kb][lane];
            #pragma unroll
            for (int jn2 = 0; jn2 < 4; jn2++) {
                uint4 kf = KFc[wn * 4 + jn2][kb][lane];
                #pragma unroll
                for (int im = 0; im < 2; im++) {
                    mma_f16(acc[im][2 * jn2 + 0], (const uint32_t*)&a[im], (const uint32_t*)&kf.x);
                    mma_f16(acc[im][2 * jn2 + 1], (const uint32_t*)&a[im], (const uint32_t*)&kf.z);
                }
            }
        }

        #pragma unroll
        for (int im = 0; im < 2; im++) {
            int mb = wm * 32 + im * 16;
            #pragma unroll
            for (int jn = 0; jn < 8; jn++) {
                int n = n0 + wn * 64 + jn * 8 + 2 * kq;
                float pu0 = ex2(acc[im][jn][0] * sc);
                float pu1 = ex2(acc[im][jn][1] * sc);
                float pu2 = ex2(acc[im][jn][2] * sc);
                float pu3 = ex2(acc[im][jn][3] * sc);
                l_acc[im][0] += pu0 + pu1;
                l_acc[im][1] += pu2 + pu3;
                *(float2*)&pstrip[(size_t)(mb + g) * SEQ + n]     = make_float2(pu0, pu1);
                *(float2*)&pstrip[(size_t)(mb + g + 8) * SEQ + n] = make_float2(pu2, pu3);
            }
        }

        if (has_next) scores_store_k(sm.KF[(iter + 1) & 1], tid, k_lo, k_hi);
        __syncthreads();
    }

    #pragma unroll
    for (int im = 0; im < 2; im++)
        #pragma unroll
        for (int rh = 0; rh < 2; rh++) {
            l_acc[im][rh] += __shfl_xor_sync(0xffffffff, l_acc[im][rh], 1);
            l_acc[im][rh] += __shfl_xor_sync(0xffffffff, l_acc[im][rh], 2);
        }
    if (kq == 0) {
        #pragma unroll
        for (int im = 0; im < 2; im++)
            #pragma unroll
            for (int rh = 0; rh < 2; rh++)
                sm.red[wn][wm * 32 + im * 16 + rh * 8 + g] = l_acc[im][rh];
    }
    __syncthreads();
    if (tid < 128) {
        float l = sm.red[0][tid] + sm.red[1][tid];
        invl_out[(size_t)bh * SEQ + m0 + tid] = 1.0f / l;
    }
}

// ---------------------------------------------------------------------------
// PV + normalization (fp16 k16): normalized p feeds the MMA (fp16-safe range)
// ---------------------------------------------------------------------------
struct PvSmem {
    uint4 PF[2][8][2][33];    // P A-frags [buf][mt][kb16][lane]
    uint4 VF[2][4][2][33];    // paired V B-frags [buf][nt2][kb16][lane]
    float sinvl[128];
};

__device__ __forceinline__ void pv_load_regs(
    const float* __restrict__ pbase, const float* __restrict__ vbase,
    int k0, int tid, float4* p_lo, float4* p_hi, float4& v_lo, float4& v_hi)
{
    #pragma unroll
    for (int i = 0; i < 2; i++) {
        int idx = tid + i * 256;
        int rp = idx >> 3, c4 = (idx & 7) * 4;
        const float* a0 = &pbase[(size_t)((rp >> 3) * 16 + (rp & 7)) * SEQ + k0 + c4];
        p_lo[i] = *(const float4*)a0;
        p_hi[i] = *(const float4*)(a0 + 8 * SEQ);
    }
    // V: key-row pairs (2*rp, 2*rp+1)
    int rp = tid >> 4, c4 = (tid & 15) * 4;
    const float* v0 = &vbase[(size_t)(k0 + 2 * rp) * D_MODEL + c4];
    v_lo = *(const float4*)v0;
    v_hi = *(const float4*)(v0 + D_MODEL);
}

__device__ __forceinline__ void pv_store_smem(
    uint4 (*PF)[2][33], uint4 (*VF)[2][33], float* pbase, const float* sinvl,
    int k0, int tid, int write_p,
    const float4* p_lo, const float4* p_hi, const float4& v_lo, const float4& v_hi)
{
    #pragma unroll
    for (int i = 0; i < 2; i++) {
        int idx = tid + i * 256;
        int rp = idx >> 3, c4 = (idx & 7) * 4;
        int mt = rp >> 3, r8 = rp & 7;
        float il0 = sinvl[mt * 16 + r8];
        float il1 = sinvl[mt * 16 + r8 + 8];
        float4 pn_lo = make_float4(p_lo[i].x * il0, p_lo[i].y * il0,
                                   p_lo[i].z * il0, p_lo[i].w * il0);
        float4 pn_hi = make_float4(p_hi[i].x * il1, p_hi[i].y * il1,
                                   p_hi[i].z * il1, p_hi[i].w * il1);
        if (write_p) {
            float* a0 = &pbase[(size_t)(mt * 16 + r8) * SEQ + k0 + c4];
            *(float4*)a0 = pn_lo;
            *(float4*)(a0 + 8 * SEQ) = pn_hi;
        }
        // Store normalized p fragments (range [0,1], fp16-safe)
        a_frag_store((uint32_t*)&PF[mt][c4 >> 4][0], r8, c4, pn_lo, pn_hi);
    }
    {
        int rp = tid >> 4, c4 = (tid & 15) * 4;
        int kb = rp >> 3;
        int tt = rp & 7;
        int kqv = tt & 3, regsel = tt >> 2;
        float ve[4] = {v_lo.x, v_lo.y, v_lo.z, v_lo.w};
        float vo[4] = {v_hi.x, v_hi.y, v_hi.z, v_hi.w};
        #pragma unroll
        for (int j = 0; j < 4; j++) {
            int d = c4 + j;
            int nt = d >> 3, gg = d & 7;
            uint32_t* w = (uint32_t*)&VF[nt >> 1][kb][0];
            w[(gg * 4 + kqv) * 4 + (nt & 1) * 2 + regsel] = f2h2(ve[j], vo[j]);
        }
    }
}

__global__ void __launch_bounds__(256, 2)
pv_norm_tc(float* attn, const float* __restrict__ vb,
           const float* __restrict__ invl_in, float* __restrict__ ctx, int write_p)
{
    extern __shared__ char smem_raw[];
    PvSmem& sm = *(PvSmem*)smem_raw;

    const int tid  = threadIdx.x;
    const int warp = tid >> 5;
    const int lane = tid & 31;
    const int g    = lane >> 2;
    const int kq   = lane & 3;
    const int wm   = warp >> 1;
    const int wn   = warp & 1;

    const int bh = blockIdx.z;
    const int b  = bh >> 4;
    const int h  = bh & 15;
    const int m0 = blockIdx.x * 128;

    float* pbase = attn + ((size_t)bh * SEQ + m0) * SEQ;
    const float* vbase = vb + (size_t)b * SEQ * D_MODEL + h * HEADDIM;

    if (tid < 128) sm.sinvl[tid] = invl_in[(size_t)bh * SEQ + m0 + tid];
    __syncthreads();

    float acc[2][4][4] = {};
    float4 p_lo[2], p_hi[2], v_lo, v_hi;

    pv_load_regs(pbase, vbase, 0, tid, p_lo, p_hi, v_lo, v_hi);
    pv_store_smem(sm.PF[0], sm.VF[0], pbase, sm.sinvl, 0, tid, write_p,
                  p_lo, p_hi, v_lo, v_hi);
    __syncthreads();

    const int NT = SEQ / 32;
    for (int kt = 0; kt < NT; kt++) {
        const bool has_next = (kt + 1 < NT);
        if (has_next)
            pv_load_regs(pbase, vbase, (kt + 1) * 32, tid, p_lo, p_hi, v_lo, v_hi);

        uint4 (*PFc)[2][33] = sm.PF[kt & 1];
        uint4 (*VFc)[2][33] = sm.VF[kt & 1];
        #pragma unroll
        for (int kb = 0; kb < 2; kb++) {
            uint4 a[2];
            a[0] = PFc[wm * 2 + 0][kb][lane];
            a[1] = PFc[wm * 2 + 1][kb][lane];
            #pragma unroll
            for (int jn2 = 0; jn2 < 2; jn2++) {
                uint4 vf = VFc[wn * 2 + jn2][kb][lane];
                #pragma unroll
                for (int im = 0; im < 2; im++) {
                    mma_f16(acc[im][2 * jn2 + 0], (const uint32_t*)&a[im], (const uint32_t*)&vf.x);
                    mma_f16(acc[im][2 * jn2 + 1], (const uint32_t*)&a[im], (const uint32_t*)&vf.z);
                }
            }
        }

        if (has_next)
            pv_store_smem(sm.PF[(kt + 1) & 1], sm.VF[(kt + 1) & 1], pbase, sm.sinvl,
                          (kt + 1) * 32, tid, write_p, p_lo, p_hi, v_lo, v_hi);
        __syncthreads();
    }

    // O is already normalized (p was normalized before MMA)
    #pragma unroll
    for (int im = 0; im < 2; im++) {
        int mr = wm * 32 + im * 16;
        int mb = b * SEQ + m0 + mr;
        #pragma unroll
        for (int jn = 0; jn < 4; jn++) {
            int n = h * HEADDIM + wn * 32 + jn * 8 + 2 * kq;
            float* p0 = &ctx[(size_t)(mb + g) * D_MODEL + n];
            float* p1 = &ctx[(size_t)(mb + g + 8) * D_MODEL + n];
            p0[0] = acc[im][jn][0]; p0[1] = acc[im][jn][1];
            p1[0] = acc[im][jn][2]; p1[1] = acc[im][jn][3];
        }
    }
}

// ---------------------------------------------------------------------------
// Launch
// ---------------------------------------------------------------------------
extern "C" void kernel_launch(void* const* d_in, const int* in_sizes, int n_in,
                              void* d_out, int out_size)
{
    const float* Q     = (const float*)d_in[0];
    const float* Wq    = (const float*)d_in[1];
    const float* bq    = (const float*)d_in[2];
    const float* Wk    = (const float*)d_in[3];
    const float* bk    = (const float*)d_in[4];
    const float* Wv    = (const float*)d_in[5];
    const float* bv    = (const float*)d_in[6];
    const float* Wo    = (const float*)d_in[7];
    const float* bo    = (const float*)d_in[8];
    const float* scale = (const float*)d_in[9];

    const int M = in_sizes[0] / D_MODEL;
    const int B = M / SEQ;

    float* out = (float*)d_out;

    float *qp, *kp, *vp, *cp, *ap, *ilp;
    cudaGetSymbolAddress((void**)&qp, g_q);
    cudaGetSymbolAddress((void**)&kp, g_k);
    cudaGetSymbolAddress((void**)&vp, g_v);
    cudaGetSymbolAddress((void**)&cp, g_ctx);
    cudaGetSymbolAddress((void**)&ap, g_attn);
    cudaGetSymbolAddress((void**)&ilp, g_invl);

    const size_t out_elems = (size_t)M * D_MODEL;
    const int write_p = ((size_t)out_size > out_elems) ? 1 : 0;
    float* attn = write_p ? (out + out_elems) : ap;

    const int gemm_smem   = (int)(2 * sizeof(GemmSmem));
    const int scores_smem = (int)sizeof(ScoresSmem);
    const int pv_smem     = (int)sizeof(PvSmem);
    cudaFuncSetAttribute(qkv_proj_tc, cudaFuncAttributeMaxDynamicSharedMemorySize, gemm_smem);
    cudaFuncSetAttribute(gemm_bias_tc, cudaFuncAttributeMaxDynamicSharedMemorySize, gemm_smem);
    cudaFuncSetAttribute(scores_exp_tc, cudaFuncAttributeMaxDynamicSharedMemorySize, scores_smem);
    cudaFuncSetAttribute(pv_norm_tc, cudaFuncAttributeMaxDynamicSharedMemorySize, pv_smem);

    dim3 gqkv(D_MODEL / 128, M / 128, 3);
    qkv_proj_tc<<<gqkv, 256, gemm_smem>>>(Q, Wq, bq, Wk, bk, Wv, bv, qp, kp, vp);

    dim3 gsc(SEQ / 128, B * NHEADS);
    scores_exp_tc<<<gsc, 256, scores_smem>>>(qp, kp, scale, attn, ilp);

    dim3 gpv(SEQ / 128, 1, B * NHEADS);
    pv_norm_tc<<<gpv, 256, pv_smem>>>(attn, vp, ilp, cp, write_p);

    dim3 gproj(D_MODEL / 128, M / 128);
    gemm_bias_tc<<<gproj, 256, gemm_smem>>>(cp, Wo, bo, out);
}

// round 14
// speedup vs baseline: 1.6225x; 1.1017x over previous
#include <cuda_runtime.h>
#include <cuda_bf16.h>
#include <cuda_fp16.h>
#include <math.h>
#include <stdint.h>

#define D_MODEL 1024
#define SEQ     2048
#define NHEADS  16
#define HEADDIM 64
#define MAXB    2

// ---------------------------------------------------------------------------
// Device scratch
// ---------------------------------------------------------------------------
__device__ float g_q[MAXB * SEQ * D_MODEL];
__device__ float g_k[MAXB * SEQ * D_MODEL];
__device__ float g_v[MAXB * SEQ * D_MODEL];
__device__ float g_ctx[MAXB * SEQ * D_MODEL];
__device__ float g_attn[(size_t)MAXB * NHEADS * SEQ * SEQ];

// ---------------------------------------------------------------------------
// helpers
// ---------------------------------------------------------------------------
__device__ __forceinline__ uint32_t f2h2(float a, float b) {
    __half2 h = __floats2half2_rn(a, b);
    return *(uint32_t*)&h;
}

__device__ __forceinline__ float ex2(float x) {
    float r;
    asm("ex2.approx.f32 %0, %1;" : "=f"(r) : "f"(x));
    return r;
}

__device__ __forceinline__ void mma_f16(float* c, const uint32_t* a, const uint32_t* b) {
    asm("mma.sync.aligned.m16n8k16.row.col.f32.f16.f16.f32 "
        "{%0,%1,%2,%3}, {%4,%5,%6,%7}, {%8,%9}, {%0,%1,%2,%3};"
        : "+f"(c[0]), "+f"(c[1]), "+f"(c[2]), "+f"(c[3])
        : "r"(a[0]), "r"(a[1]), "r"(a[2]), "r"(a[3]), "r"(b[0]), "r"(b[1]));
}

// ---------------------------------------------------------------------------
// Projection GEMM (R13, passing): fp16 k16, ping-pong, register staging
// ---------------------------------------------------------------------------
struct GemmSmem {
    uint4 AF[8][2][33];
    uint4 BF[8][2][33];
};

__device__ __forceinline__ void gemm_load_regs(
    const float* __restrict__ A, const float* __restrict__ W,
    int m0, int n0, int k0, int tid,
    float4* a_lo, float4* a_hi, float4* b_lo, float4* b_hi)
{
    #pragma unroll
    for (int i = 0; i < 2; i++) {
        int idx = tid + i * 256;
        int rp = idx >> 3, c4 = (idx & 7) * 4;
        const float* a0 = &A[(size_t)(m0 + (rp >> 3) * 16 + (rp & 7)) * D_MODEL + k0 + c4];
        a_lo[i] = *(const float4*)a0;
        a_hi[i] = *(const float4*)(a0 + 8 * D_MODEL);
        int rp2 = idx >> 5, c42 = (idx & 31) * 4;
        const float* b0 = &W[(size_t)(k0 + 2 * rp2) * D_MODEL + n0 + c42];
        b_lo[i] = *(const float4*)b0;
        b_hi[i] = *(const float4*)(b0 + D_MODEL);
    }
}

__device__ __forceinline__ void a_frag_store(
    uint32_t* w, int r8, int c4, const float4& vlo, const float4& vhi)
{
    int cc  = c4 & 15;
    int kq0 = (cc & 7) >> 1;
    int rb  = (cc >= 8) ? 2 : 0;
    int l0 = (r8 * 4 + kq0) * 4;
    int l1 = (r8 * 4 + kq0 + 1) * 4;
    w[l0 + rb]     = f2h2(vlo.x, vlo.y);
    w[l0 + rb + 1] = f2h2(vhi.x, vhi.y);
    w[l1 + rb]     = f2h2(vlo.z, vlo.w);
    w[l1 + rb + 1] = f2h2(vhi.z, vhi.w);
}

__device__ __forceinline__ void gemm_store_smem(
    GemmSmem& s, int tid,
    const float4* a_lo, const float4* a_hi, const float4* b_lo, const float4* b_hi)
{
    #pragma unroll
    for (int i = 0; i < 2; i++) {
        int idx = tid + i * 256;
        int rp = idx >> 3, c4 = (idx & 7) * 4;
        int mt = rp >> 3, r8 = rp & 7;
        a_frag_store((uint32_t*)&s.AF[mt][c4 >> 4][0], r8, c4, a_lo[i], a_hi[i]);

        int rp2 = idx >> 5, c42 = (idx & 31) * 4;
        int kb = rp2 >> 3;
        int tt = rp2 & 7;
        int kq = tt & 3, regsel = tt >> 2;
        float be[4] = {b_lo[i].x, b_lo[i].y, b_lo[i].z, b_lo[i].w};
        float bo[4] = {b_hi[i].x, b_hi[i].y, b_hi[i].z, b_hi[i].w};
        #pragma unroll
        for (int j = 0; j < 4; j++) {
            int n = c42 + j;
            int nt = n >> 3, gg = n & 7;
            uint32_t* w = (uint32_t*)&s.BF[nt >> 1][kb][0];
            w[(gg * 4 + kq) * 4 + (nt & 1) * 2 + regsel] = f2h2(be[j], bo[j]);
        }
    }
}

__device__ __forceinline__ void gemm_body(
    GemmSmem* bufs, const float* __restrict__ A, const float* __restrict__ W,
    const float* __restrict__ bias, float* __restrict__ C, int m0, int n0)
{
    const int tid  = threadIdx.x;
    const int warp = tid >> 5;
    const int lane = tid & 31;
    const int g    = lane >> 2;
    const int kq   = lane & 3;
    const int wm   = warp >> 1;
    const int wn   = warp & 1;

    float acc[2][8][4] = {};
    float4 a_lo[2], a_hi[2], b_lo[2], b_hi[2];

    gemm_load_regs(A, W, m0, n0, 0, tid, a_lo, a_hi, b_lo, b_hi);
    gemm_store_smem(bufs[0], tid, a_lo, a_hi, b_lo, b_hi);
    __syncthreads();

    const int NT = D_MODEL / 32;
    for (int kt = 0; kt < NT; kt++) {
        GemmSmem& cur = bufs[kt & 1];
        const bool has_next = (kt + 1 < NT);
        if (has_next)
            gemm_load_regs(A, W, m0, n0, (kt + 1) * 32, tid, a_lo, a_hi, b_lo, b_hi);

        #pragma unroll
        for (int kb = 0; kb < 2; kb++) {
            uint4 a[2];
            a[0] = cur.AF[wm * 2 + 0][kb][lane];
            a[1] = cur.AF[wm * 2 + 1][kb][lane];
            #pragma unroll
            for (int jn2 = 0; jn2 < 4; jn2++) {
                uint4 b2 = cur.BF[wn * 4 + jn2][kb][lane];
                #pragma unroll
                for (int im = 0; im < 2; im++) {
                    mma_f16(acc[im][2 * jn2 + 0], (const uint32_t*)&a[im], (const uint32_t*)&b2.x);
                    mma_f16(acc[im][2 * jn2 + 1], (const uint32_t*)&a[im], (const uint32_t*)&b2.z);
                }
            }
        }

        if (has_next)
            gemm_store_smem(bufs[(kt + 1) & 1], tid, a_lo, a_hi, b_lo, b_hi);
        __syncthreads();
    }

    #pragma unroll
    for (int im = 0; im < 2; im++) {
        int mb = m0 + wm * 32 + im * 16;
        #pragma unroll
        for (int jn = 0; jn < 8; jn++) {
            int n = n0 + wn * 64 + jn * 8 + 2 * kq;
            float b0 = bias[n], b1 = bias[n + 1];
            float* p0 = &C[(size_t)(mb + g) * D_MODEL + n];
            float* p1 = &C[(size_t)(mb + g + 8) * D_MODEL + n];
            p0[0] = acc[im][jn][0] + b0; p0[1] = acc[im][jn][1] + b1;
            p1[0] = acc[im][jn][2] + b0; p1[1] = acc[im][jn][3] + b1;
        }
    }
}

__global__ void __launch_bounds__(256, 2)
qkv_proj_tc(const float* __restrict__ A,
            const float* __restrict__ Wq, const float* __restrict__ bq,
            const float* __restrict__ Wk, const float* __restrict__ bk,
            const float* __restrict__ Wv, const float* __restrict__ bv,
            float* __restrict__ oq, float* __restrict__ ok, float* __restrict__ ov)
{
    extern __shared__ char smem_raw[];
    GemmSmem* bufs = (GemmSmem*)smem_raw;
    const int z = blockIdx.z;
    const float* W    = (z == 0) ? Wq : (z == 1) ? Wk : Wv;
    const float* bias = (z == 0) ? bq : (z == 1) ? bk : bv;
    float*       C    = (z == 0) ? oq : (z == 1) ? ok : ov;
    gemm_body(bufs, A, W, bias, C, blockIdx.y * 128, blockIdx.x * 128);
}

__global__ void __launch_bounds__(256, 2)
gemm_bias_tc(const float* __restrict__ A, const float* __restrict__ W,
             const float* __restrict__ bias, float* __restrict__ C)
{
    extern __shared__ char smem_raw[];
    GemmSmem* bufs = (GemmSmem*)smem_raw;
    gemm_body(bufs, A, W, bias, C, blockIdx.y * 128, blockIdx.x * 128);
}

// ---------------------------------------------------------------------------
// Fused attention, fp16 k16, two sweeps. CTA = 128 rows x 2048 keys, 256 thr.
// ---------------------------------------------------------------------------
struct FusedSmem {
    uint4 QF[8][4][33];     // Q A-frags [mt][kb16][lane]
    uint4 KFa[8][4][33];    // K B-frags buffer A [nt2][kb16][lane]
    uint4 KFb[8][4][33];    // K B-frags buffer B (sweep-1 ping-pong)
    uint4 VF[4][8][33];     // V B-frags [nt2(d)][kb16(key)][lane]
    uint4 PF[8][8][33];     // P A-frags [mt][kbp16(key)][lane]
    float red[2][128];
    float sinvl[128];
};

__device__ __forceinline__ void fa_load_k_regs(
    const float* __restrict__ kbase, int n0, int tid, float4* k_lo, float4* k_hi)
{
    #pragma unroll
    for (int i = 0; i < 4; i++) {
        int idx = tid + i * 256;
        int n  = idx >> 3;
        int c8 = (idx & 7) * 8;
        const float* p = &kbase[(size_t)(n0 + n) * D_MODEL + c8];
        k_lo[i] = *(const float4*)p;
        k_hi[i] = *(const float4*)(p + 4);
    }
}

__device__ __forceinline__ void fa_store_k(
    uint4 (*KF)[4][33], int tid, const float4* k_lo, const float4* k_hi)
{
    #pragma unroll
    for (int i = 0; i < 4; i++) {
        int idx = tid + i * 256;
        int n  = idx >> 3;
        int c8 = (idx & 7) * 8;
        int nt = n >> 3, gg = n & 7;
        int nt2 = nt >> 1, half = nt & 1;
        int kb = c8 >> 4;
        int regsel = (c8 >> 3) & 1;
        uint32_t* w = (uint32_t*)&KF[nt2][kb][0];
        w[(gg * 4 + 0) * 4 + half * 2 + regsel] = f2h2(k_lo[i].x, k_lo[i].y);
        w[(gg * 4 + 1) * 4 + half * 2 + regsel] = f2h2(k_lo[i].z, k_lo[i].w);
        w[(gg * 4 + 2) * 4 + half * 2 + regsel] = f2h2(k_hi[i].x, k_hi[i].y);
        w[(gg * 4 + 3) * 4 + half * 2 + regsel] = f2h2(k_hi[i].z, k_hi[i].w);
    }
}

// Direct (unstaged) V tile load+fragstore: 128 keys x 64 d
__device__ __forceinline__ void fa_loadstore_v(
    uint4 (*VF)[8][33], const float* __restrict__ vbase, int n0, int tid)
{
    #pragma unroll
    for (int i = 0; i < 4; i++) {
        int idx = tid + i * 256;
        int rp = idx >> 4;            // key pair 0..63
        int c4 = (idx & 15) * 4;      // d 0..60
        const float* p = &vbase[(size_t)(n0 + 2 * rp) * D_MODEL + c4];
        float4 ve = *(const float4*)p;
        float4 vo = *(const float4*)(p + D_MODEL);
        int kb = rp >> 3;             // 0..7
        int tt = rp & 7;
        int kqv = tt & 3, regsel = tt >> 2;
        float e[4] = {ve.x, ve.y, ve.z, ve.w};
        float o[4] = {vo.x, vo.y, vo.z, vo.w};
        #pragma unroll
        for (int j = 0; j < 4; j++) {
            int d = c4 + j;
            int nt = d >> 3, gg = d & 7;
            uint32_t* w = (uint32_t*)&VF[nt >> 1][kb][0];
            w[(gg * 4 + kqv) * 4 + (nt & 1) * 2 + regsel] = f2h2(e[j], o[j]);
        }
    }
}

__global__ void __launch_bounds__(256, 2)
attn_fused(const float* __restrict__ qb, const float* __restrict__ kb_,
           const float* __restrict__ vb, const float* __restrict__ scale_ptr,
           float* __restrict__ attn, float* __restrict__ ctx)
{
    extern __shared__ char smem_raw[];
    FusedSmem& sm = *(FusedSmem*)smem_raw;

    const int tid  = threadIdx.x;
    const int warp = tid >> 5;
    const int lane = tid & 31;
    const int g    = lane >> 2;
    const int kq   = lane & 3;
    const int wm   = warp >> 1;   // 0..3
    const int wn   = warp & 1;    // 0..1

    const int bh = blockIdx.y;
    const int b  = bh >> 4;
    const int h  = bh & 15;
    const int m0 = blockIdx.x * 128;

    const float sc = scale_ptr[0] * 1.44269504088896f;

    const float* qbase = qb  + (size_t)(b * SEQ + m0) * D_MODEL + h * HEADDIM;
    const float* kbase = kb_ + (size_t)b * SEQ * D_MODEL + h * HEADDIM;
    const float* vbase = vb  + (size_t)b * SEQ * D_MODEL + h * HEADDIM;
    float* pstrip = attn + ((size_t)bh * SEQ + m0) * SEQ;

    // ---- Q strip 128x64 -> QF (once) ----
    #pragma unroll
    for (int k0 = 0; k0 < 64; k0 += 32) {
        #pragma unroll
        for (int i = 0; i < 2; i++) {
            int idx = tid + i * 256;
            int rp = idx >> 3;
            int c4 = (idx & 7) * 4;
            int mt = rp >> 3;
            int r8 = rp & 7;
            const float* a0 = &qbase[(size_t)(mt * 16 + r8) * D_MODEL + k0 + c4];
            float4 vlo = *(const float4*)a0;
            float4 vhi = *(const float4*)(a0 + 8 * D_MODEL);
            a_frag_store((uint32_t*)&sm.QF[mt][(k0 + c4) >> 4][0], r8, c4, vlo, vhi);
        }
    }

    const int NIT = SEQ / 128;

    // ================= Sweep 1: row sums (staged ping-pong K) =================
    {
        float l_acc[2][2] = {};
        float4 k_lo[4], k_hi[4];

        fa_load_k_regs(kbase, 0, tid, k_lo, k_hi);
        fa_store_k(sm.KFa, tid, k_lo, k_hi);
        __syncthreads();

        for (int iter = 0; iter < NIT; iter++) {
            const bool has_next = (iter + 1 < NIT);
            if (has_next) fa_load_k_regs(kbase, (iter + 1) * 128, tid, k_lo, k_hi);

            uint4 (*KFc)[4][33] = (iter & 1) ? sm.KFb : sm.KFa;
            float acc[2][8][4] = {};
            #pragma unroll
            for (int kb = 0; kb < 4; kb++) {
                uint4 a[2];
                a[0] = sm.QF[wm * 2 + 0][kb][lane];
                a[1] = sm.QF[wm * 2 + 1][kb][lane];
                #pragma unroll
                for (int jn2 = 0; jn2 < 4; jn2++) {
                    uint4 kf = KFc[wn * 4 + jn2][kb][lane];
                    #pragma unroll
                    for (int im = 0; im < 2; im++) {
                        mma_f16(acc[im][2 * jn2 + 0], (const uint32_t*)&a[im], (const uint32_t*)&kf.x);
                        mma_f16(acc[im][2 * jn2 + 1], (const uint32_t*)&a[im], (const uint32_t*)&kf.z);
                    }
                }
            }
            #pragma unroll
            for (int im = 0; im < 2; im++)
                #pragma unroll
                for (int jn = 0; jn < 8; jn++) {
                    l_acc[im][0] += ex2(acc[im][jn][0] * sc) + ex2(acc[im][jn][1] * sc);
                    l_acc[im][1] += ex2(acc[im][jn][2] * sc) + ex2(acc[im][jn][3] * sc);
                }

            if (has_next) fa_store_k((iter & 1) ? sm.KFa : sm.KFb, tid, k_lo, k_hi);
            __syncthreads();
        }

        #pragma unroll
        for (int im = 0; im < 2; im++)
            #pragma unroll
            for (int rh = 0; rh < 2; rh++) {
                l_acc[im][rh] += __shfl_xor_sync(0xffffffff, l_acc[im][rh], 1);
                l_acc[im][rh] += __shfl_xor_sync(0xffffffff, l_acc[im][rh], 2);
            }
        if (kq == 0) {
            #pragma unroll
            for (int im = 0; im < 2; im++)
                #pragma unroll
                for (int rh = 0; rh < 2; rh++)
                    sm.red[wn][wm * 32 + im * 16 + rh * 8 + g] = l_acc[im][rh];
        }
        __syncthreads();
        if (tid < 128)
            sm.sinvl[tid] = 1.0f / (sm.red[0][tid] + sm.red[1][tid]);
        __syncthreads();
    }

    // ================= Sweep 2: write normalized P, accumulate O =================
    float acc_o[2][4][4] = {};
    float il[2][2];
    #pragma unroll
    for (int im = 0; im < 2; im++) {
        il[im][0] = sm.sinvl[wm * 32 + im * 16 + g];
        il[im][1] = sm.sinvl[wm * 32 + im * 16 + g + 8];
    }

    for (int iter = 0; iter < NIT; iter++) {
        const int n0 = iter * 128;

        // K + V frag loads (unstaged; L2-hot after sweep 1 / sibling CTAs)
        {
            float4 k_lo[4], k_hi[4];
            fa_load_k_regs(kbase, n0, tid, k_lo, k_hi);
            fa_store_k(sm.KFa, tid, k_lo, k_hi);
        }
        fa_loadstore_v(sm.VF, vbase, n0, tid);
        __syncthreads();

        // --- S MMA ---
        float acc[2][8][4] = {};
        #pragma unroll
        for (int kb = 0; kb < 4; kb++) {
            uint4 a[2];
            a[0] = sm.QF[wm * 2 + 0][kb][lane];
            a[1] = sm.QF[wm * 2 + 1][kb][lane];
            #pragma unroll
            for (int jn2 = 0; jn2 < 4; jn2++) {
                uint4 kf = sm.KFa[wn * 4 + jn2][kb][lane];
                #pragma unroll
                for (int im = 0; im < 2; im++) {
                    mma_f16(acc[im][2 * jn2 + 0], (const uint32_t*)&a[im], (const uint32_t*)&kf.x);
                    mma_f16(acc[im][2 * jn2 + 1], (const uint32_t*)&a[im], (const uint32_t*)&kf.z);
                }
            }
        }

        // --- exp * invl, write P once, scatter p-frags to PF ---
        #pragma unroll
        for (int im = 0; im < 2; im++) {
            int mt = wm * 2 + im;
            int mb = wm * 32 + im * 16;
            #pragma unroll
            for (int jn = 0; jn < 8; jn++) {
                int c = wn * 64 + jn * 8 + 2 * kq;
                float p0 = ex2(acc[im][jn][0] * sc) * il[im][0];
                float p1 = ex2(acc[im][jn][1] * sc) * il[im][0];
                float p2 = ex2(acc[im][jn][2] * sc) * il[im][1];
                float p3 = ex2(acc[im][jn][3] * sc) * il[im][1];
                *(float2*)&pstrip[(size_t)(mb + g) * SEQ + n0 + c]     = make_float2(p0, p1);
                *(float2*)&pstrip[(size_t)(mb + g + 8) * SEQ + n0 + c] = make_float2(p2, p3);
                int kbp = wn * 4 + (jn >> 1);
                uint32_t* pfb = (uint32_t*)&sm.PF[mt][kbp][0];
                int base = (g * 4 + kq) * 4 + (jn & 1) * 2;
                pfb[base]     = f2h2(p0, p1);
                pfb[base + 1] = f2h2(p2, p3);
            }
        }
        __syncthreads();   // PF complete

        // --- PV MMA: O += P(tile) @ V(tile) ---
        #pragma unroll
        for (int kb = 0; kb < 8; kb++) {
            uint4 a[2];
            a[0] = sm.PF[wm * 2 + 0][kb][lane];
            a[1] = sm.PF[wm * 2 + 1][kb][lane];
            #pragma unroll
            for (int jn2 = 0; jn2 < 2; jn2++) {
                uint4 vf = sm.VF[wn * 2 + jn2][kb][lane];
                #pragma unroll
                for (int im = 0; im < 2; im++) {
                    mma_f16(acc_o[im][2 * jn2 + 0], (const uint32_t*)&a[im], (const uint32_t*)&vf.x);
                    mma_f16(acc_o[im][2 * jn2 + 1], (const uint32_t*)&a[im], (const uint32_t*)&vf.z);
                }
            }
        }
        __syncthreads();   // KF/VF/PF reads done before next overwrite
    }

    // ---- write O (already normalized) ----
    #pragma unroll
    for (int im = 0; im < 2; im++) {
        int mb = b * SEQ + m0 + wm * 32 + im * 16;
        #pragma unroll
        for (int jn = 0; jn < 4; jn++) {
            int d = h * HEADDIM + wn * 32 + jn * 8 + 2 * kq;
            float* p0 = &ctx[(size_t)(mb + g) * D_MODEL + d];
            float* p1 = &ctx[(size_t)(mb + g + 8) * D_MODEL + d];
            p0[0] = acc_o[im][jn][0]; p0[1] = acc_o[im][jn][1];
            p1[0] = acc_o[im][jn][2]; p1[1] = acc_o[im][jn][3];
        }
    }
}

// ---------------------------------------------------------------------------
// Launch
// ---------------------------------------------------------------------------
extern "C" void kernel_launch(void* const* d_in, const int* in_sizes, int n_in,
                              void* d_out, int out_size)
{
    const float* Q     = (const float*)d_in[0];
    const float* Wq    = (const float*)d_in[1];
    const float* bq    = (const float*)d_in[2];
    const float* Wk    = (const float*)d_in[3];
    const float* bk    = (const float*)d_in[4];
    const float* Wv    = (const float*)d_in[5];
    const float* bv    = (const float*)d_in[6];
    const float* Wo    = (const float*)d_in[7];
    const float* bo    = (const float*)d_in[8];
    const float* scale = (const float*)d_in[9];

    const int M = in_sizes[0] / D_MODEL;
    const int B = M / SEQ;

    float* out = (float*)d_out;

    float *qp, *kp, *vp, *cp, *ap;
    cudaGetSymbolAddress((void**)&qp, g_q);
    cudaGetSymbolAddress((void**)&kp, g_k);
    cudaGetSymbolAddress((void**)&vp, g_v);
    cudaGetSymbolAddress((void**)&cp, g_ctx);
    cudaGetSymbolAddress((void**)&ap, g_attn);

    const size_t out_elems = (size_t)M * D_MODEL;
    float* attn = ((size_t)out_size > out_elems) ? (out + out_elems) : ap;

    const int gemm_smem  = (int)(2 * sizeof(GemmSmem));
    const int fused_smem = (int)sizeof(FusedSmem);
    cudaFuncSetAttribute(qkv_proj_tc, cudaFuncAttributeMaxDynamicSharedMemorySize, gemm_smem);
    cudaFuncSetAttribute(gemm_bias_tc, cudaFuncAttributeMaxDynamicSharedMemorySize, gemm_smem);
    cudaFuncSetAttribute(attn_fused, cudaFuncAttributeMaxDynamicSharedMemorySize, fused_smem);

    dim3 gqkv(D_MODEL / 128, M / 128, 3);
    qkv_proj_tc<<<gqkv, 256, gemm_smem>>>(Q, Wq, bq, Wk, bk, Wv, bv, qp, kp, vp);

    dim3 gfa(SEQ / 128, B * NHEADS);   // (16, 32)
    attn_fused<<<gfa, 256, fused_smem>>>(qp, kp, vp, scale, attn, cp);

    dim3 gproj(D_MODEL / 128, M / 128);
    gemm_bias_tc<<<gproj, 256, gemm_smem>>>(cp, Wo, bo, out);
}

// round 15
// speedup vs baseline: 1.7972x; 1.1077x over previous
#include <cuda_runtime.h>
#include <cuda_bf16.h>
#include <cuda_fp16.h>
#include <math.h>
#include <stdint.h>

#define D_MODEL 1024
#define SEQ     2048
#define NHEADS  16
#define HEADDIM 64
#define MAXB    2

// ---------------------------------------------------------------------------
// Device scratch
// ---------------------------------------------------------------------------
__device__ float g_q[MAXB * SEQ * D_MODEL];
__device__ float g_k[MAXB * SEQ * D_MODEL];
__device__ float g_v[MAXB * SEQ * D_MODEL];
__device__ float g_attn[(size_t)MAXB * NHEADS * SEQ * SEQ];
// fragment buffers (uint4 granularity): [strip][kt][512]
__device__ uint4 g_afrag[32 * 32 * 512];            // input A fragments
__device__ uint4 g_bfrag[4 * 8 * 32 * 512];         // Wq,Wk,Wv,Wo B-fragments
__device__ uint4 g_ofrag[32 * 32 * 512];            // attention O fragments

// ---------------------------------------------------------------------------
// helpers
// ---------------------------------------------------------------------------
__device__ __forceinline__ uint32_t f2h2(float a, float b) {
    __half2 h = __floats2half2_rn(a, b);
    return *(uint32_t*)&h;
}

__device__ __forceinline__ float ex2(float x) {
    float r;
    asm("ex2.approx.f32 %0, %1;" : "=f"(r) : "f"(x));
    return r;
}

__device__ __forceinline__ void mma_f16(float* c, const uint32_t* a, const uint32_t* b) {
    asm("mma.sync.aligned.m16n8k16.row.col.f32.f16.f16.f32 "
        "{%0,%1,%2,%3}, {%4,%5,%6,%7}, {%8,%9}, {%0,%1,%2,%3};"
        : "+f"(c[0]), "+f"(c[1]), "+f"(c[2]), "+f"(c[3])
        : "r"(a[0]), "r"(a[1]), "r"(a[2]), "r"(a[3]), "r"(b[0]), "r"(b[1]));
}

__device__ __forceinline__ void a_frag_store(
    uint32_t* w, int r8, int c4, const float4& vlo, const float4& vhi)
{
    int cc  = c4 & 15;
    int kq0 = (cc & 7) >> 1;
    int rb  = (cc >= 8) ? 2 : 0;
    int l0 = (r8 * 4 + kq0) * 4;
    int l1 = (r8 * 4 + kq0 + 1) * 4;
    w[l0 + rb]     = f2h2(vlo.x, vlo.y);
    w[l0 + rb + 1] = f2h2(vhi.x, vhi.y);
    w[l1 + rb]     = f2h2(vlo.z, vlo.w);
    w[l1 + rb + 1] = f2h2(vhi.z, vhi.w);
}

// ---------------------------------------------------------------------------
// Prep: build fp16 fragment buffers for A and the 4 weight matrices.
// z=0: A (A-fragment layout), z=1..4: W[z-1] (B-fragment layout).
// Each CTA handles one (strip, kt) 128x32 tile; scatter in SMEM, copy out.
// ---------------------------------------------------------------------------
__global__ void __launch_bounds__(256)
prep_frags(const float* __restrict__ A,
           const float* __restrict__ Wq, const float* __restrict__ Wk,
           const float* __restrict__ Wv, const float* __restrict__ Wo,
           uint4* __restrict__ afg, uint4* __restrict__ bfg, int mstrips)
{
    __shared__ uint4 F[8][2][33];
    const int z     = blockIdx.z;
    const int strip = blockIdx.y;
    const int kt    = blockIdx.x;
    const int tid   = threadIdx.x;
    if (z == 0 && strip >= mstrips) return;
    if (z > 0 && strip >= 8) return;

    const int k0 = kt * 32;

    if (z == 0) {
        const int m0 = strip * 128;
        #pragma unroll
        for (int i = 0; i < 2; i++) {
            int idx = tid + i * 256;
            int rp = idx >> 3, c4 = (idx & 7) * 4;
            int mt = rp >> 3, r8 = rp & 7;
            const float* a0 = &A[(size_t)(m0 + mt * 16 + r8) * D_MODEL + k0 + c4];
            float4 vlo = *(const float4*)a0;
            float4 vhi = *(const float4*)(a0 + 8 * D_MODEL);
            a_frag_store((uint32_t*)&F[mt][c4 >> 4][0], r8, c4, vlo, vhi);
        }
    } else {
        const float* W = (z == 1) ? Wq : (z == 2) ? Wk : (z == 3) ? Wv : Wo;
        const int n0 = strip * 128;
        #pragma unroll
        for (int i = 0; i < 2; i++) {
            int idx = tid + i * 256;
            int rp2 = idx >> 5, c42 = (idx & 31) * 4;
            const float* b0 = &W[(size_t)(k0 + 2 * rp2) * D_MODEL + n0 + c42];
            float4 blo = *(const float4*)b0;
            float4 bhi = *(const float4*)(b0 + D_MODEL);
            int kb = rp2 >> 3;
            int tt = rp2 & 7;
            int kq = tt & 3, regsel = tt >> 2;
            float be[4] = {blo.x, blo.y, blo.z, blo.w};
            float bo_[4] = {bhi.x, bhi.y, bhi.z, bhi.w};
            #pragma unroll
            for (int j = 0; j < 4; j++) {
                int n = c42 + j;
                int nt = n >> 3, gg = n & 7;
                uint32_t* w = (uint32_t*)&F[nt >> 1][kb][0];
                w[(gg * 4 + kq) * 4 + (nt & 1) * 2 + regsel] = f2h2(be[j], bo_[j]);
            }
        }
    }
    __syncthreads();

    uint4* dst = (z == 0)
        ? afg + ((size_t)strip * 32 + kt) * 512
        : bfg + (((size_t)(z - 1) * 8 + strip) * 32 + kt) * 512;
    #pragma unroll
    for (int j = tid; j < 512; j += 256)
        dst[j] = F[j >> 6][(j >> 5) & 1][j & 31];
}

// ---------------------------------------------------------------------------
// Fragment GEMM: loads prebuilt fragments (LDG.128 -> STS.128 -> LDS -> MMA)
// ---------------------------------------------------------------------------
struct GemmSmem {
    uint4 AF[8][2][33];
    uint4 BF[8][2][33];
};

__device__ __forceinline__ void frag_sts(GemmSmem& s, int tid,
                                         const uint4* sa, const uint4* sb)
{
    #pragma unroll
    for (int i = 0; i < 2; i++) {
        int j = tid + i * 256;
        s.AF[j >> 6][(j >> 5) & 1][j & 31] = sa[i];
        s.BF[j >> 6][(j >> 5) & 1][j & 31] = sb[i];
    }
}

__device__ __forceinline__ void gemm_frag_body(
    GemmSmem* bufs, const uint4* __restrict__ Ag, const uint4* __restrict__ Bg,
    const float* __restrict__ bias, float* __restrict__ C, int m0, int n0)
{
    const int tid  = threadIdx.x;
    const int warp = tid >> 5;
    const int lane = tid & 31;
    const int g    = lane >> 2;
    const int kq   = lane & 3;
    const int wm   = warp >> 1;
    const int wn   = warp & 1;

    float acc[2][8][4] = {};
    uint4 sa[2], sb[2];

    #pragma unroll
    for (int i = 0; i < 2; i++) {
        sa[i] = Ag[tid + i * 256];
        sb[i] = Bg[tid + i * 256];
    }
    frag_sts(bufs[0], tid, sa, sb);
    __syncthreads();

    const int NT = D_MODEL / 32;
    for (int kt = 0; kt < NT; kt++) {
        GemmSmem& cur = bufs[kt & 1];
        const bool has_next = (kt + 1 < NT);
        if (has_next) {
            #pragma unroll
            for (int i = 0; i < 2; i++) {
                sa[i] = Ag[(kt + 1) * 512 + tid + i * 256];
                sb[i] = Bg[(kt + 1) * 512 + tid + i * 256];
            }
        }

        #pragma unroll
        for (int kb = 0; kb < 2; kb++) {
            uint4 a[2];
            a[0] = cur.AF[wm * 2 + 0][kb][lane];
            a[1] = cur.AF[wm * 2 + 1][kb][lane];
            #pragma unroll
            for (int jn2 = 0; jn2 < 4; jn2++) {
                uint4 b2 = cur.BF[wn * 4 + jn2][kb][lane];
                #pragma unroll
                for (int im = 0; im < 2; im++) {
                    mma_f16(acc[im][2 * jn2 + 0], (const uint32_t*)&a[im], (const uint32_t*)&b2.x);
                    mma_f16(acc[im][2 * jn2 + 1], (const uint32_t*)&a[im], (const uint32_t*)&b2.z);
                }
            }
        }

        if (has_next)
            frag_sts(bufs[(kt + 1) & 1], tid, sa, sb);
        __syncthreads();
    }

    #pragma unroll
    for (int im = 0; im < 2; im++) {
        int mb = m0 + wm * 32 + im * 16;
        #pragma unroll
        for (int jn = 0; jn < 8; jn++) {
            int n = n0 + wn * 64 + jn * 8 + 2 * kq;
            float b0 = bias[n], b1 = bias[n + 1];
            float* p0 = &C[(size_t)(mb + g) * D_MODEL + n];
            float* p1 = &C[(size_t)(mb + g + 8) * D_MODEL + n];
            p0[0] = acc[im][jn][0] + b0; p0[1] = acc[im][jn][1] + b1;
            p1[0] = acc[im][jn][2] + b0; p1[1] = acc[im][jn][3] + b1;
        }
    }
}

__global__ void __launch_bounds__(256, 2)
qkv_frag(const uint4* __restrict__ afg, const uint4* __restrict__ bfg,
         const float* __restrict__ bq, const float* __restrict__ bk,
         const float* __restrict__ bv,
         float* __restrict__ oq, float* __restrict__ ok, float* __restrict__ ov)
{
    extern __shared__ char smem_raw[];
    GemmSmem* bufs = (GemmSmem*)smem_raw;
    const int z = blockIdx.z;
    const float* bias = (z == 0) ? bq : (z == 1) ? bk : bv;
    float*       C    = (z == 0) ? oq : (z == 1) ? ok : ov;
    const uint4* Ag = afg + (size_t)blockIdx.y * 32 * 512;
    const uint4* Bg = bfg + (((size_t)z * 8 + blockIdx.x) * 32) * 512;
    gemm_frag_body(bufs, Ag, Bg, bias, C, blockIdx.y * 128, blockIdx.x * 128);
}

__global__ void __launch_bounds__(256, 2)
gemm_frag(const uint4* __restrict__ ofg, const uint4* __restrict__ bfg,
          const float* __restrict__ bias, float* __restrict__ C)
{
    extern __shared__ char smem_raw[];
    GemmSmem* bufs = (GemmSmem*)smem_raw;
    const uint4* Ag = ofg + (size_t)blockIdx.y * 32 * 512;
    const uint4* Bg = bfg + (((size_t)3 * 8 + blockIdx.x) * 32) * 512;
    gemm_frag_body(bufs, Ag, Bg, bias, C, blockIdx.y * 128, blockIdx.x * 128);
}

// ---------------------------------------------------------------------------
// Fused attention (R14, passing) — epilogue now writes O as fp16 fragments
// ---------------------------------------------------------------------------
struct FusedSmem {
    uint4 QF[8][4][33];
    uint4 KFa[8][4][33];
    uint4 KFb[8][4][33];
    uint4 VF[4][8][33];
    uint4 PF[8][8][33];
    float red[2][128];
    float sinvl[128];
};

__device__ __forceinline__ void fa_load_k_regs(
    const float* __restrict__ kbase, int n0, int tid, float4* k_lo, float4* k_hi)
{
    #pragma unroll
    for (int i = 0; i < 4; i++) {
        int idx = tid + i * 256;
        int n  = idx >> 3;
        int c8 = (idx & 7) * 8;
        const float* p = &kbase[(size_t)(n0 + n) * D_MODEL + c8];
        k_lo[i] = *(const float4*)p;
        k_hi[i] = *(const float4*)(p + 4);
    }
}

__device__ __forceinline__ void fa_store_k(
    uint4 (*KF)[4][33], int tid, const float4* k_lo, const float4* k_hi)
{
    #pragma unroll
    for (int i = 0; i < 4; i++) {
        int idx = tid + i * 256;
        int n  = idx >> 3;
        int c8 = (idx & 7) * 8;
        int nt = n >> 3, gg = n & 7;
        int nt2 = nt >> 1, half = nt & 1;
        int kb = c8 >> 4;
        int regsel = (c8 >> 3) & 1;
        uint32_t* w = (uint32_t*)&KF[nt2][kb][0];
        w[(gg * 4 + 0) * 4 + half * 2 + regsel] = f2h2(k_lo[i].x, k_lo[i].y);
        w[(gg * 4 + 1) * 4 + half * 2 + regsel] = f2h2(k_lo[i].z, k_lo[i].w);
        w[(gg * 4 + 2) * 4 + half * 2 + regsel] = f2h2(k_hi[i].x, k_hi[i].y);
        w[(gg * 4 + 3) * 4 + half * 2 + regsel] = f2h2(k_hi[i].z, k_hi[i].w);
    }
}

__device__ __forceinline__ void fa_loadstore_v(
    uint4 (*VF)[8][33], const float* __restrict__ vbase, int n0, int tid)
{
    #pragma unroll
    for (int i = 0; i < 4; i++) {
        int idx = tid + i * 256;
        int rp = idx >> 4;
        int c4 = (idx & 15) * 4;
        const float* p = &vbase[(size_t)(n0 + 2 * rp) * D_MODEL + c4];
        float4 ve = *(const float4*)p;
        float4 vo = *(const float4*)(p + D_MODEL);
        int kb = rp >> 3;
        int tt = rp & 7;
        int kqv = tt & 3, regsel = tt >> 2;
        float e[4] = {ve.x, ve.y, ve.z, ve.w};
        float o[4] = {vo.x, vo.y, vo.z, vo.w};
        #pragma unroll
        for (int j = 0; j < 4; j++) {
            int d = c4 + j;
            int nt = d >> 3, gg = d & 7;
            uint32_t* w = (uint32_t*)&VF[nt >> 1][kb][0];
            w[(gg * 4 + kqv) * 4 + (nt & 1) * 2 + regsel] = f2h2(e[j], o[j]);
        }
    }
}

__global__ void __launch_bounds__(256, 2)
attn_fused(const float* __restrict__ qb, const float* __restrict__ kb_,
           const float* __restrict__ vb, const float* __restrict__ scale_ptr,
           float* __restrict__ attn, uint4* __restrict__ ofg)
{
    extern __shared__ char smem_raw[];
    FusedSmem& sm = *(FusedSmem*)smem_raw;

    const int tid  = threadIdx.x;
    const int warp = tid >> 5;
    const int lane = tid & 31;
    const int g    = lane >> 2;
    const int kq   = lane & 3;
    const int wm   = warp >> 1;
    const int wn   = warp & 1;

    const int bh = blockIdx.y;
    const int b  = bh >> 4;
    const int h  = bh & 15;
    const int m0 = blockIdx.x * 128;

    const float sc = scale_ptr[0] * 1.44269504088896f;

    const float* qbase = qb  + (size_t)(b * SEQ + m0) * D_MODEL + h * HEADDIM;
    const float* kbase = kb_ + (size_t)b * SEQ * D_MODEL + h * HEADDIM;
    const float* vbase = vb  + (size_t)b * SEQ * D_MODEL + h * HEADDIM;
    float* pstrip = attn + ((size_t)bh * SEQ + m0) * SEQ;

    // ---- Q strip 128x64 -> QF ----
    #pragma unroll
    for (int k0 = 0; k0 < 64; k0 += 32) {
        #pragma unroll
        for (int i = 0; i < 2; i++) {
            int idx = tid + i * 256;
            int rp = idx >> 3;
            int c4 = (idx & 7) * 4;
            int mt = rp >> 3;
            int r8 = rp & 7;
            const float* a0 = &qbase[(size_t)(mt * 16 + r8) * D_MODEL + k0 + c4];
            float4 vlo = *(const float4*)a0;
            float4 vhi = *(const float4*)(a0 + 8 * D_MODEL);
            a_frag_store((uint32_t*)&sm.QF[mt][(k0 + c4) >> 4][0], r8, c4, vlo, vhi);
        }
    }

    const int NIT = SEQ / 128;

    // ================= Sweep 1: row sums =================
    {
        float l_acc[2][2] = {};
        float4 k_lo[4], k_hi[4];

        fa_load_k_regs(kbase, 0, tid, k_lo, k_hi);
        fa_store_k(sm.KFa, tid, k_lo, k_hi);
        __syncthreads();

        for (int iter = 0; iter < NIT; iter++) {
            const bool has_next = (iter + 1 < NIT);
            if (has_next) fa_load_k_regs(kbase, (iter + 1) * 128, tid, k_lo, k_hi);

            uint4 (*KFc)[4][33] = (iter & 1) ? sm.KFb : sm.KFa;
            float acc[2][8][4] = {};
            #pragma unroll
            for (int kb = 0; kb < 4; kb++) {
                uint4 a[2];
                a[0] = sm.QF[wm * 2 + 0][kb][lane];
                a[1] = sm.QF[wm * 2 + 1][kb][lane];
                #pragma unroll
                for (int jn2 = 0; jn2 < 4; jn2++) {
                    uint4 kf = KFc[wn * 4 + jn2][kb][lane];
                    #pragma unroll
                    for (int im = 0; im < 2; im++) {
                        mma_f16(acc[im][2 * jn2 + 0], (const uint32_t*)&a[im], (const uint32_t*)&kf.x);
                        mma_f16(acc[im][2 * jn2 + 1], (const uint32_t*)&a[im], (const uint32_t*)&kf.z);
                    }
                }
            }
            #pragma unroll
            for (int im = 0; im < 2; im++)
                #pragma unroll
                for (int jn = 0; jn < 8; jn++) {
                    l_acc[im][0] += ex2(acc[im][jn][0] * sc) + ex2(acc[im][jn][1] * sc);
                    l_acc[im][1] += ex2(acc[im][jn][2] * sc) + ex2(acc[im][jn][3] * sc);
                }

            if (has_next) fa_store_k((iter & 1) ? sm.KFa : sm.KFb, tid, k_lo, k_hi);
            __syncthreads();
        }

        #pragma unroll
        for (int im = 0; im < 2; im++)
            #pragma unroll
            for (int rh = 0; rh < 2; rh++) {
                l_acc[im][rh] += __shfl_xor_sync(0xffffffff, l_acc[im][rh], 1);
                l_acc[im][rh] += __shfl_xor_sync(0xffffffff, l_acc[im][rh], 2);
            }
        if (kq == 0) {
            #pragma unroll
            for (int im = 0; im < 2; im++)
                #pragma unroll
                for (int rh = 0; rh < 2; rh++)
                    sm.red[wn][wm * 32 + im * 16 + rh * 8 + g] = l_acc[im][rh];
        }
        __syncthreads();
        if (tid < 128)
            sm.sinvl[tid] = 1.0f / (sm.red[0][tid] + sm.red[1][tid]);
        __syncthreads();
    }

    // ================= Sweep 2: write normalized P, accumulate O =================
    float acc_o[2][4][4] = {};
    float il[2][2];
    #pragma unroll
    for (int im = 0; im < 2; im++) {
        il[im][0] = sm.sinvl[wm * 32 + im * 16 + g];
        il[im][1] = sm.sinvl[wm * 32 + im * 16 + g + 8];
    }

    for (int iter = 0; iter < NIT; iter++) {
        const int n0 = iter * 128;

        {
            float4 k_lo[4], k_hi[4];
            fa_load_k_regs(kbase, n0, tid, k_lo, k_hi);
            fa_store_k(sm.KFa, tid, k_lo, k_hi);
        }
        fa_loadstore_v(sm.VF, vbase, n0, tid);
        __syncthreads();

        float acc[2][8][4] = {};
        #pragma unroll
        for (int kb = 0; kb < 4; kb++) {
            uint4 a[2];
            a[0] = sm.QF[wm * 2 + 0][kb][lane];
            a[1] = sm.QF[wm * 2 + 1][kb][lane];
            #pragma unroll
            for (int jn2 = 0; jn2 < 4; jn2++) {
                uint4 kf = sm.KFa[wn * 4 + jn2][kb][lane];
                #pragma unroll
                for (int im = 0; im < 2; im++) {
                    mma_f16(acc[im][2 * jn2 + 0], (const uint32_t*)&a[im], (const uint32_t*)&kf.x);
                    mma_f16(acc[im][2 * jn2 + 1], (const uint32_t*)&a[im], (const uint32_t*)&kf.z);
                }
            }
        }

        #pragma unroll
        for (int im = 0; im < 2; im++) {
            int mt = wm * 2 + im;
            int mb = wm * 32 + im * 16;
            #pragma unroll
            for (int jn = 0; jn < 8; jn++) {
                int c = wn * 64 + jn * 8 + 2 * kq;
                float p0 = ex2(acc[im][jn][0] * sc) * il[im][0];
                float p1 = ex2(acc[im][jn][1] * sc) * il[im][0];
                float p2 = ex2(acc[im][jn][2] * sc) * il[im][1];
                float p3 = ex2(acc[im][jn][3] * sc) * il[im][1];
                *(float2*)&pstrip[(size_t)(mb + g) * SEQ + n0 + c]     = make_float2(p0, p1);
                *(float2*)&pstrip[(size_t)(mb + g + 8) * SEQ + n0 + c] = make_float2(p2, p3);
                int kbp = wn * 4 + (jn >> 1);
                uint32_t* pfb = (uint32_t*)&sm.PF[mt][kbp][0];
                int base = (g * 4 + kq) * 4 + (jn & 1) * 2;
                pfb[base]     = f2h2(p0, p1);
                pfb[base + 1] = f2h2(p2, p3);
            }
        }
        __syncthreads();

        #pragma unroll
        for (int kb = 0; kb < 8; kb++) {
            uint4 a[2];
            a[0] = sm.PF[wm * 2 + 0][kb][lane];
            a[1] = sm.PF[wm * 2 + 1][kb][lane];
            #pragma unroll
            for (int jn2 = 0; jn2 < 2; jn2++) {
                uint4 vf = sm.VF[wn * 2 + jn2][kb][lane];
                #pragma unroll
                for (int im = 0; im < 2; im++) {
                    mma_f16(acc_o[im][2 * jn2 + 0], (const uint32_t*)&a[im], (const uint32_t*)&vf.x);
                    mma_f16(acc_o[im][2 * jn2 + 1], (const uint32_t*)&a[im], (const uint32_t*)&vf.z);
                }
            }
        }
        __syncthreads();
    }

    // ---- write O directly as fp16 A-fragments for the output projection ----
    // thread owns its own lane slot: OFg[strip][kt32 = h*2+wn][(mt*2+kb)*32 + lane]
    {
        const int strip = (b * SEQ + m0) >> 7;
        const int kt32  = h * 2 + wn;
        uint4* obase = ofg + ((size_t)strip * 32 + kt32) * 512;
        #pragma unroll
        for (int im = 0; im < 2; im++) {
            int mt = wm * 2 + im;
            #pragma unroll
            for (int kb = 0; kb < 2; kb++) {
                // kb=0 from jn 0,1 ; kb=1 from jn 2,3  (jn = 2*kb + {0,1})
                float* a0 = acc_o[im][2 * kb + 0];
                float* a1 = acc_o[im][2 * kb + 1];
                uint4 u;
                u.x = f2h2(a0[0], a0[1]);   // row g,   jn even (rb=0): words 0,1
                u.y = f2h2(a0[2], a0[3]);   // row g+8
                u.z = f2h2(a1[0], a1[1]);   // row g,   jn odd (rb=2): words 2,3
                u.w = f2h2(a1[2], a1[3]);   // row g+8
                obase[(mt * 2 + kb) * 32 + lane] = u;
            }
        }
    }
}

// ---------------------------------------------------------------------------
// Launch
// ---------------------------------------------------------------------------
extern "C" void kernel_launch(void* const* d_in, const int* in_sizes, int n_in,
                              void* d_out, int out_size)
{
    const float* Q     = (const float*)d_in[0];
    const float* Wq    = (const float*)d_in[1];
    const float* bq    = (const float*)d_in[2];
    const float* Wk    = (const float*)d_in[3];
    const float* bk    = (const float*)d_in[4];
    const float* Wv    = (const float*)d_in[5];
    const float* bv    = (const float*)d_in[6];
    const float* Wo    = (const float*)d_in[7];
    const float* bo    = (const float*)d_in[8];
    const float* scale = (const float*)d_in[9];

    const int M = in_sizes[0] / D_MODEL;
    const int B = M / SEQ;
    const int mstrips = M / 128;

    float* out = (float*)d_out;

    float *qp, *kp, *vp, *ap;
    uint4 *afp, *bfp, *ofp;
    cudaGetSymbolAddress((void**)&qp, g_q);
    cudaGetSymbolAddress((void**)&kp, g_k);
    cudaGetSymbolAddress((void**)&vp, g_v);
    cudaGetSymbolAddress((void**)&ap, g_attn);
    cudaGetSymbolAddress((void**)&afp, g_afrag);
    cudaGetSymbolAddress((void**)&bfp, g_bfrag);
    cudaGetSymbolAddress((void**)&ofp, g_ofrag);

    const size_t out_elems = (size_t)M * D_MODEL;
    float* attn = ((size_t)out_size > out_elems) ? (out + out_elems) : ap;

    const int gemm_smem  = (int)(2 * sizeof(GemmSmem));
    const int fused_smem = (int)sizeof(FusedSmem);
    cudaFuncSetAttribute(qkv_frag, cudaFuncAttributeMaxDynamicSharedMemorySize, gemm_smem);
    cudaFuncSetAttribute(gemm_frag, cudaFuncAttributeMaxDynamicSharedMemorySize, gemm_smem);
    cudaFuncSetAttribute(attn_fused, cudaFuncAttributeMaxDynamicSharedMemorySize, fused_smem);

    // 1) fragment prep (A + 4 weights)
    dim3 gprep(32, mstrips > 8 ? mstrips : 8, 5);
    prep_frags<<<gprep, 256>>>(Q, Wq, Wk, Wv, Wo, afp, bfp, mstrips);

    // 2) QKV projections from fragments
    dim3 gqkv(D_MODEL / 128, mstrips, 3);
    qkv_frag<<<gqkv, 256, gemm_smem>>>(afp, bfp, bq, bk, bv, qp, kp, vp);

    // 3) fused attention (writes normalized P + O fragments)
    dim3 gfa(SEQ / 128, B * NHEADS);
    attn_fused<<<gfa, 256, fused_smem>>>(qp, kp, vp, scale, attn, ofp);

    // 4) output projection from O fragments
    dim3 gproj(D_MODEL / 128, mstrips);
    gemm_frag<<<gproj, 256, gemm_smem>>>(ofp, bfp, bo, out);
}

// round 16
// speedup vs baseline: 2.0855x; 1.1604x over previous
#include <cuda_runtime.h>
#include <cuda_bf16.h>
#include <cuda_fp16.h>
#include <math.h>
#include <stdint.h>

#define D_MODEL 1024
#define SEQ     2048
#define NHEADS  16
#define HEADDIM 64
#define MAXB    2

// ---------------------------------------------------------------------------
// Device scratch
// ---------------------------------------------------------------------------
__device__ float g_q[MAXB * SEQ * D_MODEL];
__device__ float g_k[MAXB * SEQ * D_MODEL];
__device__ float g_v[MAXB * SEQ * D_MODEL];
__device__ float g_attn[(size_t)MAXB * NHEADS * SEQ * SEQ];
__device__ uint4 g_afrag[32 * 32 * 512];            // input A fragments
__device__ uint4 g_bfrag[4 * 8 * 32 * 512];         // Wq,Wk,Wv,Wo B-fragments
__device__ uint4 g_ofrag[32 * 32 * 512];            // attention O fragments
// attention operand fragments: [bh][tile16][1024]
__device__ uint4 g_qfrag[MAXB * NHEADS * 16 * 1024];
__device__ uint4 g_kfrag[MAXB * NHEADS * 16 * 1024];
__device__ uint4 g_vfrag[MAXB * NHEADS * 16 * 1024];

// ---------------------------------------------------------------------------
// helpers
// ---------------------------------------------------------------------------
__device__ __forceinline__ uint32_t f2h2(float a, float b) {
    __half2 h = __floats2half2_rn(a, b);
    return *(uint32_t*)&h;
}

__device__ __forceinline__ float ex2(float x) {
    float r;
    asm("ex2.approx.f32 %0, %1;" : "=f"(r) : "f"(x));
    return r;
}

__device__ __forceinline__ void mma_f16(float* c, const uint32_t* a, const uint32_t* b) {
    asm("mma.sync.aligned.m16n8k16.row.col.f32.f16.f16.f32 "
        "{%0,%1,%2,%3}, {%4,%5,%6,%7}, {%8,%9}, {%0,%1,%2,%3};"
        : "+f"(c[0]), "+f"(c[1]), "+f"(c[2]), "+f"(c[3])
        : "r"(a[0]), "r"(a[1]), "r"(a[2]), "r"(a[3]), "r"(b[0]), "r"(b[1]));
}

__device__ __forceinline__ void a_frag_store(
    uint32_t* w, int r8, int c4, const float4& vlo, const float4& vhi)
{
    int cc  = c4 & 15;
    int kq0 = (cc & 7) >> 1;
    int rb  = (cc >= 8) ? 2 : 0;
    int l0 = (r8 * 4 + kq0) * 4;
    int l1 = (r8 * 4 + kq0 + 1) * 4;
    w[l0 + rb]     = f2h2(vlo.x, vlo.y);
    w[l0 + rb + 1] = f2h2(vhi.x, vhi.y);
    w[l1 + rb]     = f2h2(vlo.z, vlo.w);
    w[l1 + rb + 1] = f2h2(vhi.z, vhi.w);
}

// ---------------------------------------------------------------------------
// Prep: fragment buffers for input A and the 4 weight matrices (R15, passing)
// ---------------------------------------------------------------------------
__global__ void __launch_bounds__(256)
prep_frags(const float* __restrict__ A,
           const float* __restrict__ Wq, const float* __restrict__ Wk,
           const float* __restrict__ Wv, const float* __restrict__ Wo,
           uint4* __restrict__ afg, uint4* __restrict__ bfg, int mstrips)
{
    __shared__ uint4 F[8][2][33];
    const int z     = blockIdx.z;
    const int strip = blockIdx.y;
    const int kt    = blockIdx.x;
    const int tid   = threadIdx.x;
    if (z == 0 && strip >= mstrips) return;
    if (z > 0 && strip >= 8) return;

    const int k0 = kt * 32;

    if (z == 0) {
        const int m0 = strip * 128;
        #pragma unroll
        for (int i = 0; i < 2; i++) {
            int idx = tid + i * 256;
            int rp = idx >> 3, c4 = (idx & 7) * 4;
            int mt = rp >> 3, r8 = rp & 7;
            const float* a0 = &A[(size_t)(m0 + mt * 16 + r8) * D_MODEL + k0 + c4];
            float4 vlo = *(const float4*)a0;
            float4 vhi = *(const float4*)(a0 + 8 * D_MODEL);
            a_frag_store((uint32_t*)&F[mt][c4 >> 4][0], r8, c4, vlo, vhi);
        }
    } else {
        const float* W = (z == 1) ? Wq : (z == 2) ? Wk : (z == 3) ? Wv : Wo;
        const int n0 = strip * 128;
        #pragma unroll
        for (int i = 0; i < 2; i++) {
            int idx = tid + i * 256;
            int rp2 = idx >> 5, c42 = (idx & 31) * 4;
            const float* b0 = &W[(size_t)(k0 + 2 * rp2) * D_MODEL + n0 + c42];
            float4 blo = *(const float4*)b0;
            float4 bhi = *(const float4*)(b0 + D_MODEL);
            int kb = rp2 >> 3;
            int tt = rp2 & 7;
            int kq = tt & 3, regsel = tt >> 2;
            float be[4] = {blo.x, blo.y, blo.z, blo.w};
            float bo_[4] = {bhi.x, bhi.y, bhi.z, bhi.w};
            #pragma unroll
            for (int j = 0; j < 4; j++) {
                int n = c42 + j;
                int nt = n >> 3, gg = n & 7;
                uint32_t* w = (uint32_t*)&F[nt >> 1][kb][0];
                w[(gg * 4 + kq) * 4 + (nt & 1) * 2 + regsel] = f2h2(be[j], bo_[j]);
            }
        }
    }
    __syncthreads();

    uint4* dst = (z == 0)
        ? afg + ((size_t)strip * 32 + kt) * 512
        : bfg + (((size_t)(z - 1) * 8 + strip) * 32 + kt) * 512;
    #pragma unroll
    for (int j = tid; j < 512; j += 256)
        dst[j] = F[j >> 6][(j >> 5) & 1][j & 31];
}

// ---------------------------------------------------------------------------
// Fragment GEMM (R15, passing)
// ---------------------------------------------------------------------------
struct GemmSmem {
    uint4 AF[8][2][33];
    uint4 BF[8][2][33];
};

__device__ __forceinline__ void frag_sts(GemmSmem& s, int tid,
                                         const uint4* sa, const uint4* sb)
{
    #pragma unroll
    for (int i = 0; i < 2; i++) {
        int j = tid + i * 256;
        s.AF[j >> 6][(j >> 5) & 1][j & 31] = sa[i];
        s.BF[j >> 6][(j >> 5) & 1][j & 31] = sb[i];
    }
}

__device__ __forceinline__ void gemm_frag_body(
    GemmSmem* bufs, const uint4* __restrict__ Ag, const uint4* __restrict__ Bg,
    const float* __restrict__ bias, float* __restrict__ C, int m0, int n0)
{
    const int tid  = threadIdx.x;
    const int warp = tid >> 5;
    const int lane = tid & 31;
    const int g    = lane >> 2;
    const int kq   = lane & 3;
    const int wm   = warp >> 1;
    const int wn   = warp & 1;

    float acc[2][8][4] = {};
    uint4 sa[2], sb[2];

    #pragma unroll
    for (int i = 0; i < 2; i++) {
        sa[i] = Ag[tid + i * 256];
        sb[i] = Bg[tid + i * 256];
    }
    frag_sts(bufs[0], tid, sa, sb);
    __syncthreads();

    const int NT = D_MODEL / 32;
    for (int kt = 0; kt < NT; kt++) {
        GemmSmem& cur = bufs[kt & 1];
        const bool has_next = (kt + 1 < NT);
        if (has_next) {
            #pragma unroll
            for (int i = 0; i < 2; i++) {
                sa[i] = Ag[(kt + 1) * 512 + tid + i * 256];
                sb[i] = Bg[(kt + 1) * 512 + tid + i * 256];
            }
        }

        #pragma unroll
        for (int kb = 0; kb < 2; kb++) {
            uint4 a[2];
            a[0] = cur.AF[wm * 2 + 0][kb][lane];
            a[1] = cur.AF[wm * 2 + 1][kb][lane];
            #pragma unroll
            for (int jn2 = 0; jn2 < 4; jn2++) {
                uint4 b2 = cur.BF[wn * 4 + jn2][kb][lane];
                #pragma unroll
                for (int im = 0; im < 2; im++) {
                    mma_f16(acc[im][2 * jn2 + 0], (const uint32_t*)&a[im], (const uint32_t*)&b2.x);
                    mma_f16(acc[im][2 * jn2 + 1], (const uint32_t*)&a[im], (const uint32_t*)&b2.z);
                }
            }
        }

        if (has_next)
            frag_sts(bufs[(kt + 1) & 1], tid, sa, sb);
        __syncthreads();
    }

    #pragma unroll
    for (int im = 0; im < 2; im++) {
        int mb = m0 + wm * 32 + im * 16;
        #pragma unroll
        for (int jn = 0; jn < 8; jn++) {
            int n = n0 + wn * 64 + jn * 8 + 2 * kq;
            float b0 = bias[n], b1 = bias[n + 1];
            float* p0 = &C[(size_t)(mb + g) * D_MODEL + n];
            float* p1 = &C[(size_t)(mb + g + 8) * D_MODEL + n];
            p0[0] = acc[im][jn][0] + b0; p0[1] = acc[im][jn][1] + b1;
            p1[0] = acc[im][jn][2] + b0; p1[1] = acc[im][jn][3] + b1;
        }
    }
}

__global__ void __launch_bounds__(256, 2)
qkv_frag(const uint4* __restrict__ afg, const uint4* __restrict__ bfg,
         const float* __restrict__ bq, const float* __restrict__ bk,
         const float* __restrict__ bv,
         float* __restrict__ oq, float* __restrict__ ok, float* __restrict__ ov)
{
    extern __shared__ char smem_raw[];
    GemmSmem* bufs = (GemmSmem*)smem_raw;
    const int z = blockIdx.z;
    const float* bias = (z == 0) ? bq : (z == 1) ? bk : bv;
    float*       C    = (z == 0) ? oq : (z == 1) ? ok : ov;
    const uint4* Ag = afg + (size_t)blockIdx.y * 32 * 512;
    const uint4* Bg = bfg + (((size_t)z * 8 + blockIdx.x) * 32) * 512;
    gemm_frag_body(bufs, Ag, Bg, bias, C, blockIdx.y * 128, blockIdx.x * 128);
}

__global__ void __launch_bounds__(256, 2)
gemm_frag(const uint4* __restrict__ ofg, const uint4* __restrict__ bfg,
          const float* __restrict__ bias, float* __restrict__ C)
{
    extern __shared__ char smem_raw[];
    GemmSmem* bufs = (GemmSmem*)smem_raw;
    const uint4* Ag = ofg + (size_t)blockIdx.y * 32 * 512;
    const uint4* Bg = bfg + (((size_t)3 * 8 + blockIdx.x) * 32) * 512;
    gemm_frag_body(bufs, Ag, Bg, bias, C, blockIdx.y * 128, blockIdx.x * 128);
}

// ---------------------------------------------------------------------------
// Prep: attention operand fragments per (bh, 128-tile).
// z=0: Q (A-frag [8mt][4kb][32]), z=1: K (B-frag [8nt2][4kb][32]),
// z=2: V (B-frag [4nt2][8kb][32]). Packed 1024-uint4 blocks.
// ---------------------------------------------------------------------------
__global__ void __launch_bounds__(256)
prep_qkv(const float* __restrict__ qb, const float* __restrict__ kb_,
         const float* __restrict__ vb,
         uint4* __restrict__ qfg, uint4* __restrict__ kfg, uint4* __restrict__ vfg)
{
    __shared__ uint4 F[8][4][33];   // 1056 uint4, shared by all three shapes
    const int z    = blockIdx.z;
    const int bh   = blockIdx.y;
    const int tile = blockIdx.x;
    const int tid  = threadIdx.x;
    const int b = bh >> 4;
    const int h = bh & 15;

    if (z == 0) {
        const float* base = qb + (size_t)(b * SEQ + tile * 128) * D_MODEL + h * HEADDIM;
        #pragma unroll
        for (int k0 = 0; k0 < 64; k0 += 32) {
            #pragma unroll
            for (int i = 0; i < 2; i++) {
                int idx = tid + i * 256;
                int rp = idx >> 3, c4 = (idx & 7) * 4;
                int mt = rp >> 3, r8 = rp & 7;
                const float* a0 = &base[(size_t)(mt * 16 + r8) * D_MODEL + k0 + c4];
                float4 vlo = *(const float4*)a0;
                float4 vhi = *(const float4*)(a0 + 8 * D_MODEL);
                a_frag_store((uint32_t*)&F[mt][(k0 + c4) >> 4][0], r8, c4, vlo, vhi);
            }
        }
    } else if (z == 1) {
        const float* base = kb_ + (size_t)b * SEQ * D_MODEL + h * HEADDIM;
        const int n0 = tile * 128;
        #pragma unroll
        for (int i = 0; i < 4; i++) {
            int idx = tid + i * 256;
            int n  = idx >> 3;
            int c8 = (idx & 7) * 8;
            const float* p = &base[(size_t)(n0 + n) * D_MODEL + c8];
            float4 klo = *(const float4*)p;
            float4 khi = *(const float4*)(p + 4);
            int nt = n >> 3, gg = n & 7;
            int nt2 = nt >> 1, half = nt & 1;
            int kb = c8 >> 4;
            int regsel = (c8 >> 3) & 1;
            uint32_t* w = (uint32_t*)&F[nt2][kb][0];
            w[(gg * 4 + 0) * 4 + half * 2 + regsel] = f2h2(klo.x, klo.y);
            w[(gg * 4 + 1) * 4 + half * 2 + regsel] = f2h2(klo.z, klo.w);
            w[(gg * 4 + 2) * 4 + half * 2 + regsel] = f2h2(khi.x, khi.y);
            w[(gg * 4 + 3) * 4 + half * 2 + regsel] = f2h2(khi.z, khi.w);
        }
    } else {
        const float* base = vb + (size_t)b * SEQ * D_MODEL + h * HEADDIM;
        const int n0 = tile * 128;
        uint4 (*VF)[8][33] = (uint4(*)[8][33])F;
        #pragma unroll
        for (int i = 0; i < 4; i++) {
            int idx = tid + i * 256;
            int rp = idx >> 4;
            int c4 = (idx & 15) * 4;
            const float* p = &base[(size_t)(n0 + 2 * rp) * D_MODEL + c4];
            float4 ve = *(const float4*)p;
            float4 vo = *(const float4*)(p + D_MODEL);
            int kb = rp >> 3;
            int tt = rp & 7;
            int kqv = tt & 3, regsel = tt >> 2;
            float e[4] = {ve.x, ve.y, ve.z, ve.w};
            float o[4] = {vo.x, vo.y, vo.z, vo.w};
            #pragma unroll
            for (int j = 0; j < 4; j++) {
                int d = c4 + j;
                int nt = d >> 3, gg = d & 7;
                uint32_t* w = (uint32_t*)&VF[nt >> 1][kb][0];
                w[(gg * 4 + kqv) * 4 + (nt & 1) * 2 + regsel] = f2h2(e[j], o[j]);
            }
        }
    }
    __syncthreads();

    uint4* dst = ((z == 0) ? qfg : (z == 1) ? kfg : vfg)
               + ((size_t)bh * 16 + tile) * 1024;
    if (z == 2) {
        uint4 (*VF)[8][33] = (uint4(*)[8][33])F;
        #pragma unroll
        for (int j = tid; j < 1024; j += 256)
            dst[j] = VF[j >> 8][(j >> 5) & 7][j & 31];
    } else {
        #pragma unroll
        for (int j = tid; j < 1024; j += 256)
            dst[j] = F[j >> 7][(j >> 5) & 3][j & 31];
    }
}

// ---------------------------------------------------------------------------
// Fused attention: operands are prebuilt fp16 fragments.
// ---------------------------------------------------------------------------
struct FusedSmem {
    uint4 QF[8][4][33];
    uint4 KFa[8][4][33];
    uint4 KFb[8][4][33];
    uint4 VF[4][8][33];
    uint4 PF[8][8][33];
    float red[2][128];
    float sinvl[128];
};

__global__ void __launch_bounds__(256, 2)
attn_fused(const uint4* __restrict__ qfg, const uint4* __restrict__ kfg,
           const uint4* __restrict__ vfg, const float* __restrict__ scale_ptr,
           float* __restrict__ attn, uint4* __restrict__ ofg)
{
    extern __shared__ char smem_raw[];
    FusedSmem& sm = *(FusedSmem*)smem_raw;

    const int tid  = threadIdx.x;
    const int warp = tid >> 5;
    const int lane = tid & 31;
    const int g    = lane >> 2;
    const int kq   = lane & 3;
    const int wm   = warp >> 1;
    const int wn   = warp & 1;

    const int bh = blockIdx.y;
    const int b  = bh >> 4;
    const int h  = bh & 15;
    const int m0 = blockIdx.x * 128;

    const float sc = scale_ptr[0] * 1.44269504088896f;

    const uint4* Qg = qfg + ((size_t)bh * 16 + blockIdx.x) * 1024;
    const uint4* Kg = kfg + (size_t)bh * 16 * 1024;
    const uint4* Vg = vfg + (size_t)bh * 16 * 1024;
    float* pstrip = attn + ((size_t)bh * SEQ + m0) * SEQ;

    // ---- Q frags (once): 4 LDG.128 -> STS.128 per thread ----
    #pragma unroll
    for (int i = 0; i < 4; i++) {
        int j = tid + i * 256;
        sm.QF[j >> 7][(j >> 5) & 3][j & 31] = Qg[j];
    }

    const int NIT = SEQ / 128;

    // ================= Sweep 1: row sums =================
    {
        float l_acc[2][2] = {};
        uint4 kreg[4];

        #pragma unroll
        for (int i = 0; i < 4; i++) kreg[i] = Kg[tid + i * 256];
        #pragma unroll
        for (int i = 0; i < 4; i++) {
            int j = tid + i * 256;
            sm.KFa[j >> 7][(j >> 5) & 3][j & 31] = kreg[i];
        }
        __syncthreads();

        for (int iter = 0; iter < NIT; iter++) {
            const bool has_next = (iter + 1 < NIT);
            if (has_next)
                #pragma unroll
                for (int i = 0; i < 4; i++)
                    kreg[i] = Kg[(iter + 1) * 1024 + tid + i * 256];

            uint4 (*KFc)[4][33] = (iter & 1) ? sm.KFb : sm.KFa;
            float acc[2][8][4] = {};
            #pragma unroll
            for (int kb = 0; kb < 4; kb++) {
                uint4 a[2];
                a[0] = sm.QF[wm * 2 + 0][kb][lane];
                a[1] = sm.QF[wm * 2 + 1][kb][lane];
                #pragma unroll
                for (int jn2 = 0; jn2 < 4; jn2++) {
                    uint4 kf = KFc[wn * 4 + jn2][kb][lane];
                    #pragma unroll
                    for (int im = 0; im < 2; im++) {
                        mma_f16(acc[im][2 * jn2 + 0], (const uint32_t*)&a[im], (const uint32_t*)&kf.x);
                        mma_f16(acc[im][2 * jn2 + 1], (const uint32_t*)&a[im], (const uint32_t*)&kf.z);
                    }
                }
            }
            #pragma unroll
            for (int im = 0; im < 2; im++)
                #pragma unroll
                for (int jn = 0; jn < 8; jn++) {
                    l_acc[im][0] += ex2(acc[im][jn][0] * sc) + ex2(acc[im][jn][1] * sc);
                    l_acc[im][1] += ex2(acc[im][jn][2] * sc) + ex2(acc[im][jn][3] * sc);
                }

            if (has_next) {
                uint4 (*KFn)[4][33] = (iter & 1) ? sm.KFa : sm.KFb;
                #pragma unroll
                for (int i = 0; i < 4; i++) {
                    int j = tid + i * 256;
                    KFn[j >> 7][(j >> 5) & 3][j & 31] = kreg[i];
                }
            }
            __syncthreads();
        }

        #pragma unroll
        for (int im = 0; im < 2; im++)
            #pragma unroll
            for (int rh = 0; rh < 2; rh++) {
                l_acc[im][rh] += __shfl_xor_sync(0xffffffff, l_acc[im][rh], 1);
                l_acc[im][rh] += __shfl_xor_sync(0xffffffff, l_acc[im][rh], 2);
            }
        if (kq == 0) {
            #pragma unroll
            for (int im = 0; im < 2; im++)
                #pragma unroll
                for (int rh = 0; rh < 2; rh++)
                    sm.red[wn][wm * 32 + im * 16 + rh * 8 + g] = l_acc[im][rh];
        }
        __syncthreads();
        if (tid < 128)
            sm.sinvl[tid] = 1.0f / (sm.red[0][tid] + sm.red[1][tid]);
        __syncthreads();
    }

    // ================= Sweep 2: write normalized P, accumulate O =================
    float acc_o[2][4][4] = {};
    float il[2][2];
    #pragma unroll
    for (int im = 0; im < 2; im++) {
        il[im][0] = sm.sinvl[wm * 32 + im * 16 + g];
        il[im][1] = sm.sinvl[wm * 32 + im * 16 + g + 8];
    }

    for (int iter = 0; iter < NIT; iter++) {
        const int n0 = iter * 128;

        #pragma unroll
        for (int i = 0; i < 4; i++) {
            int j = tid + i * 256;
            uint4 kv = Kg[iter * 1024 + j];
            sm.KFa[j >> 7][(j >> 5) & 3][j & 31] = kv;
            uint4 vv = Vg[iter * 1024 + j];
            sm.VF[j >> 8][(j >> 5) & 7][j & 31] = vv;
        }
        __syncthreads();

        float acc[2][8][4] = {};
        #pragma unroll
        for (int kb = 0; kb < 4; kb++) {
            uint4 a[2];
            a[0] = sm.QF[wm * 2 + 0][kb][lane];
            a[1] = sm.QF[wm * 2 + 1][kb][lane];
            #pragma unroll
            for (int jn2 = 0; jn2 < 4; jn2++) {
                uint4 kf = sm.KFa[wn * 4 + jn2][kb][lane];
                #pragma unroll
                for (int im = 0; im < 2; im++) {
                    mma_f16(acc[im][2 * jn2 + 0], (const uint32_t*)&a[im], (const uint32_t*)&kf.x);
                    mma_f16(acc[im][2 * jn2 + 1], (const uint32_t*)&a[im], (const uint32_t*)&kf.z);
                }
            }
        }

        #pragma unroll
        for (int im = 0; im < 2; im++) {
            int mt = wm * 2 + im;
            int mb = wm * 32 + im * 16;
            #pragma unroll
            for (int jn = 0; jn < 8; jn++) {
                int c = wn * 64 + jn * 8 + 2 * kq;
                float p0 = ex2(acc[im][jn][0] * sc) * il[im][0];
                float p1 = ex2(acc[im][jn][1] * sc) * il[im][0];
                float p2 = ex2(acc[im][jn][2] * sc) * il[im][1];
                float p3 = ex2(acc[im][jn][3] * sc) * il[im][1];
                *(float2*)&pstrip[(size_t)(mb + g) * SEQ + n0 + c]     = make_float2(p0, p1);
                *(float2*)&pstrip[(size_t)(mb + g + 8) * SEQ + n0 + c] = make_float2(p2, p3);
                int kbp = wn * 4 + (jn >> 1);
                uint32_t* pfb = (uint32_t*)&sm.PF[mt][kbp][0];
                int base = (g * 4 + kq) * 4 + (jn & 1) * 2;
                *(uint2*)&pfb[base] = make_uint2(f2h2(p0, p1), f2h2(p2, p3));
            }
        }
        __syncthreads();

        #pragma unroll
        for (int kb = 0; kb < 8; kb++) {
            uint4 a[2];
            a[0] = sm.PF[wm * 2 + 0][kb][lane];
            a[1] = sm.PF[wm * 2 + 1][kb][lane];
            #pragma unroll
            for (int jn2 = 0; jn2 < 2; jn2++) {
                uint4 vf = sm.VF[wn * 2 + jn2][kb][lane];
                #pragma unroll
                for (int im = 0; im < 2; im++) {
                    mma_f16(acc_o[im][2 * jn2 + 0], (const uint32_t*)&a[im], (const uint32_t*)&vf.x);
                    mma_f16(acc_o[im][2 * jn2 + 1], (const uint32_t*)&a[im], (const uint32_t*)&vf.z);
                }
            }
        }
        __syncthreads();
    }

    // ---- write O directly as fp16 A-fragments for the output projection ----
    {
        const int strip = (b * SEQ + m0) >> 7;
        const int kt32  = h * 2 + wn;
        uint4* obase = ofg + ((size_t)strip * 32 + kt32) * 512;
        #pragma unroll
        for (int im = 0; im < 2; im++) {
            int mt = wm * 2 + im;
            #pragma unroll
            for (int kb = 0; kb < 2; kb++) {
                float* a0 = acc_o[im][2 * kb + 0];
                float* a1 = acc_o[im][2 * kb + 1];
                uint4 u;
                u.x = f2h2(a0[0], a0[1]);
                u.y = f2h2(a0[2], a0[3]);
                u.z = f2h2(a1[0], a1[1]);
                u.w = f2h2(a1[2], a1[3]);
                obase[(mt * 2 + kb) * 32 + lane] = u;
            }
        }
    }
}

// ---------------------------------------------------------------------------
// Launch
// ---------------------------------------------------------------------------
extern "C" void kernel_launch(void* const* d_in, const int* in_sizes, int n_in,
                              void* d_out, int out_size)
{
    const float* Q     = (const float*)d_in[0];
    const float* Wq    = (const float*)d_in[1];
    const float* bq    = (const float*)d_in[2];
    const float* Wk    = (const float*)d_in[3];
    const float* bk    = (const float*)d_in[4];
    const float* Wv    = (const float*)d_in[5];
    const float* bv    = (const float*)d_in[6];
    const float* Wo    = (const float*)d_in[7];
    const float* bo    = (const float*)d_in[8];
    const float* scale = (const float*)d_in[9];

    const int M = in_sizes[0] / D_MODEL;
    const int B = M / SEQ;
    const int mstrips = M / 128;

    float* out = (float*)d_out;

    float *qp, *kp, *vp, *ap;
    uint4 *afp, *bfp, *ofp, *qfp, *kfp, *vfp;
    cudaGetSymbolAddress((void**)&qp, g_q);
    cudaGetSymbolAddress((void**)&kp, g_k);
    cudaGetSymbolAddress((void**)&vp, g_v);
    cudaGetSymbolAddress((void**)&ap, g_attn);
    cudaGetSymbolAddress((void**)&afp, g_afrag);
    cudaGetSymbolAddress((void**)&bfp, g_bfrag);
    cudaGetSymbolAddress((void**)&ofp, g_ofrag);
    cudaGetSymbolAddress((void**)&qfp, g_qfrag);
    cudaGetSymbolAddress((void**)&kfp, g_kfrag);
    cudaGetSymbolAddress((void**)&vfp, g_vfrag);

    const size_t out_elems = (size_t)M * D_MODEL;
    float* attn = ((size_t)out_size > out_elems) ? (out + out_elems) : ap;

    const int gemm_smem  = (int)(2 * sizeof(GemmSmem));
    const int fused_smem = (int)sizeof(FusedSmem);
    cudaFuncSetAttribute(qkv_frag, cudaFuncAttributeMaxDynamicSharedMemorySize, gemm_smem);
    cudaFuncSetAttribute(gemm_frag, cudaFuncAttributeMaxDynamicSharedMemorySize, gemm_smem);
    cudaFuncSetAttribute(attn_fused, cudaFuncAttributeMaxDynamicSharedMemorySize, fused_smem);

    // 1) fragment prep (A + 4 weights)
    dim3 gprep(32, mstrips > 8 ? mstrips : 8, 5);
    prep_frags<<<gprep, 256>>>(Q, Wq, Wk, Wv, Wo, afp, bfp, mstrips);

    // 2) QKV projections from fragments
    dim3 gqkv(D_MODEL / 128, mstrips, 3);
    qkv_frag<<<gqkv, 256, gemm_smem>>>(afp, bfp, bq, bk, bv, qp, kp, vp);

    // 3) attention operand fragment prep
    dim3 gpq(SEQ / 128, B * NHEADS, 3);
    prep_qkv<<<gpq, 256>>>(qp, kp, vp, qfp, kfp, vfp);

    // 4) fused attention on fragments
    dim3 gfa(SEQ / 128, B * NHEADS);
    attn_fused<<<gfa, 256, fused_smem>>>(qfp, kfp, vfp, scale, attn, ofp);

    // 5) output projection from O fragments
    dim3 gproj(D_MODEL / 128, mstrips);
    gemm_frag<<<gproj, 256, gemm_smem>>>(ofp, bfp, bo, out);
}